// round 2
// baseline (speedup 1.0000x reference)
#include <cuda_runtime.h>
#include <cuda_bf16.h>
#include <math.h>

// Problem constants
#define T_TOK   8192        // 4*2048 tokens
#define DIM     1024
#define HID     4096
#define NEXP    8
#define TOPK    2

// GEMM tiling
#define BM 128
#define BN 128
#define BK 8
#define TM 8
#define TN 8

// Max padded rows: 16384 + 8*(BM-1) -> round up to multiple of BM
#define ROWS_MAX 17408

// ------------------------ device scratch (static, no allocs) ------------------
__device__ float g_h[(size_t)ROWS_MAX * HID];      // GELU(x*W1+b1) per (token,expert) row
__device__ float g_o2[(size_t)ROWS_MAX * DIM];     // h*W2 per row (no bias, no prob)
__device__ int   g_tok[ROWS_MAX];                  // row -> token (-1 = padding)
__device__ int   g_row_of[T_TOK * TOPK];           // (token,k) -> row
__device__ int   g_topk[T_TOK * TOPK];             // (token,k) -> expert
__device__ float g_probs[T_TOK * TOPK];            // (token,k) -> prob
__device__ int   g_cnt[NEXP];
__device__ float g_loadf[NEXP];
__device__ int   g_off[NEXP + 1];                  // padded expert row offsets
__device__ int   g_cursor[NEXP];

// ------------------------ init ------------------------------------------------
__global__ void init_kernel() {
    int i = blockIdx.x * blockDim.x + threadIdx.x;
    if (i < ROWS_MAX) g_tok[i] = -1;
    if (i < NEXP) { g_cnt[i] = 0; g_loadf[i] = 0.0f; }
}

// ------------------------ gate: one warp per token ------------------------------
__global__ void gate_kernel(const float* __restrict__ x,
                            const float* __restrict__ gw,
                            const float* __restrict__ gb) {
    int gtid = blockIdx.x * blockDim.x + threadIdx.x;
    int t    = gtid >> 5;
    int lane = gtid & 31;
    if (t >= T_TOK) return;

    const float* xr = x + (size_t)t * DIM;
    float acc[NEXP];
#pragma unroll
    for (int e = 0; e < NEXP; e++) acc[e] = 0.0f;

    for (int i = lane; i < DIM; i += 32) {
        float xv = xr[i];
        const float* g = gw + (size_t)i * NEXP;
#pragma unroll
        for (int e = 0; e < NEXP; e++) acc[e] = fmaf(xv, g[e], acc[e]);
    }
#pragma unroll
    for (int e = 0; e < NEXP; e++) {
#pragma unroll
        for (int o = 16; o > 0; o >>= 1)
            acc[e] += __shfl_xor_sync(0xffffffffu, acc[e], o);
    }
    if (lane == 0) {
        float l[NEXP];
#pragma unroll
        for (int e = 0; e < NEXP; e++) l[e] = acc[e] + gb[e];
        // top-1 (ties -> lowest index, matching jax top_k)
        int i0 = 0;
#pragma unroll
        for (int e = 1; e < NEXP; e++) if (l[e] > l[i0]) i0 = e;
        // top-2
        int i1 = -1;
#pragma unroll
        for (int e = 0; e < NEXP; e++) {
            if (e == i0) continue;
            if (i1 < 0 || l[e] > l[i1]) i1 = e;
        }
        // softmax over the two top logits
        float e1 = expf(l[i1] - l[i0]);
        float s  = 1.0f + e1;
        float p0 = 1.0f / s;
        float p1 = e1 / s;

        g_topk[2 * t]     = i0;
        g_topk[2 * t + 1] = i1;
        g_probs[2 * t]     = p0;
        g_probs[2 * t + 1] = p1;
        atomicAdd(&g_cnt[i0], 1);
        atomicAdd(&g_cnt[i1], 1);
        atomicAdd(&g_loadf[i0], p0);
        atomicAdd(&g_loadf[i1], p1);
    }
}

// ------------------------ finalize gate: offsets + loss/load tail ----------------
__global__ void finalize_gate_kernel(float* __restrict__ out, long long out_size) {
    if (threadIdx.x == 0 && blockIdx.x == 0) {
        int off = 0;
        for (int e = 0; e < NEXP; e++) {
            g_off[e]    = off;
            g_cursor[e] = off;
            int padded  = ((g_cnt[e] + BM - 1) / BM) * BM;
            off += padded;
        }
        g_off[NEXP] = off;

        // loss + expert_load tail (only if the output buffer has room for it)
        if (out_size >= (long long)T_TOK * DIM + 1 + NEXP) {
            float* tail = out + (size_t)T_TOK * DIM;
            float loss = 0.0f;
            for (int e = 0; e < NEXP; e++) {
                float le = g_loadf[e] / (float)T_TOK;
                tail[1 + e] = le;
                float d = le - 1.0f / (float)NEXP;
                loss += d * d;
            }
            tail[0] = 0.01f * loss;
        }
    }
}

// ------------------------ scatter tokens to expert-grouped rows ------------------
__global__ void scatter_kernel() {
    int i = blockIdx.x * blockDim.x + threadIdx.x;
    if (i >= T_TOK * TOPK) return;
    int e = g_topk[i];
    int r = atomicAdd(&g_cursor[e], 1);
    g_tok[r]    = i >> 1;
    g_row_of[i] = r;
}

// ------------------------ grouped GEMM ------------------------------------------
// mode 1: C=g_h  = gelu( gather(x)[rows,DIM] * w1[e] + b1[e] ),  K=DIM, N=HID
// mode 2: C=g_o2 =        g_h[rows,HID]      * w2[e],            K=HID, N=DIM
// NOTE: scratch buffers are referenced as device symbols INSIDE the kernel —
// never passed from host (host-side shadow address bug).
__global__ void __launch_bounds__(256)
gemm_kernel(const float* __restrict__ x,
            const float* __restrict__ Wall,   // [E][K][N]
            const float* __restrict__ ball,   // [E][N]
            int K, int N, int mode) {
    __shared__ __align__(16) float As[BK][BM];
    __shared__ __align__(16) float Bs[BK][BN];

    int row0 = blockIdx.y * BM;
    int col0 = blockIdx.x * BN;

    int total = g_off[NEXP];
    if (row0 >= total) return;

    // expert lookup
    int e = 0;
#pragma unroll
    for (int i = 0; i < NEXP; i++) if (row0 >= g_off[i + 1]) e++;

    const float* Wp = Wall + (size_t)e * K * N;

    int tid = threadIdx.x;

    // A-load mapping: 128 rows x 8 cols, float4 per thread
    int aRow  = tid >> 1;
    int aCol4 = (tid & 1) * 4;
    const float* Arow;
    if (mode == 1) {
        int tk = g_tok[row0 + aRow];
        Arow = (tk >= 0) ? (x + (size_t)tk * K) : nullptr;
    } else {
        Arow = g_h + (size_t)(row0 + aRow) * K;
    }

    // B-load mapping: 8 rows x 128 cols, float4 per thread
    int bRow  = tid >> 5;
    int bCol4 = (tid & 31) * 4;

    int tx = tid & 15;   // col group
    int ty = tid >> 4;   // row group

    float acc[TM][TN];
#pragma unroll
    for (int i = 0; i < TM; i++)
#pragma unroll
        for (int j = 0; j < TN; j++) acc[i][j] = 0.0f;

    for (int kk = 0; kk < K; kk += BK) {
        float4 av = make_float4(0.f, 0.f, 0.f, 0.f);
        if (Arow) av = *(const float4*)(Arow + kk + aCol4);
        As[aCol4 + 0][aRow] = av.x;
        As[aCol4 + 1][aRow] = av.y;
        As[aCol4 + 2][aRow] = av.z;
        As[aCol4 + 3][aRow] = av.w;

        float4 bv = *(const float4*)(Wp + (size_t)(kk + bRow) * N + col0 + bCol4);
        *(float4*)&Bs[bRow][bCol4] = bv;

        __syncthreads();

#pragma unroll
        for (int k = 0; k < BK; k++) {
            float a[TM], b[TN];
#pragma unroll
            for (int i = 0; i < TM; i++) a[i] = As[k][ty * TM + i];
#pragma unroll
            for (int j = 0; j < TN; j++) b[j] = Bs[k][tx * TN + j];
#pragma unroll
            for (int i = 0; i < TM; i++)
#pragma unroll
                for (int j = 0; j < TN; j++)
                    acc[i][j] = fmaf(a[i], b[j], acc[i][j]);
        }
        __syncthreads();
    }

    // epilogue
    float* Cbase = (mode == 1) ? g_h : g_o2;
#pragma unroll
    for (int i = 0; i < TM; i++) {
        int r = row0 + ty * TM + i;
        float* crow = Cbase + (size_t)r * N + col0 + tx * TN;
        const float* brow = (mode == 1) ? (ball + (size_t)e * N + col0 + tx * TN) : nullptr;
#pragma unroll
        for (int j = 0; j < TN; j++) {
            float v = acc[i][j];
            if (mode == 1) {
                v += brow[j];
                v = 0.5f * v * (1.0f + erff(v * 0.70710678118654752f));
            }
            crow[j] = v;
        }
    }
}

// ------------------------ combine -----------------------------------------------
__global__ void combine_kernel(const float* __restrict__ b2,
                               float* __restrict__ out) {
    int i4 = blockIdx.x * blockDim.x + threadIdx.x;
    const int D4 = DIM / 4;
    if (i4 >= T_TOK * D4) return;
    int t  = i4 / D4;
    int d  = (i4 - t * D4) * 4;

    int   r0 = g_row_of[2 * t];
    int   r1 = g_row_of[2 * t + 1];
    int   e0 = g_topk[2 * t];
    int   e1 = g_topk[2 * t + 1];
    float p0 = g_probs[2 * t];
    float p1 = g_probs[2 * t + 1];

    float4 a0 = *(const float4*)(g_o2 + (size_t)r0 * DIM + d);
    float4 a1 = *(const float4*)(g_o2 + (size_t)r1 * DIM + d);
    float4 c0 = *(const float4*)(b2 + (size_t)e0 * DIM + d);
    float4 c1 = *(const float4*)(b2 + (size_t)e1 * DIM + d);

    float4 o;
    o.x = p0 * (a0.x + c0.x) + p1 * (a1.x + c1.x);
    o.y = p0 * (a0.y + c0.y) + p1 * (a1.y + c1.y);
    o.z = p0 * (a0.z + c0.z) + p1 * (a1.z + c1.z);
    o.w = p0 * (a0.w + c0.w) + p1 * (a1.w + c1.w);
    *(float4*)(out + (size_t)t * DIM + d) = o;
}

// ------------------------ launch -------------------------------------------------
extern "C" void kernel_launch(void* const* d_in, const int* in_sizes, int n_in,
                              void* d_out, int out_size) {
    const float* x      = (const float*)d_in[0];   // [4,2048,1024]
    const float* gate_w = (const float*)d_in[1];   // [1024,8]
    const float* gate_b = (const float*)d_in[2];   // [8]
    const float* w1     = (const float*)d_in[3];   // [8,1024,4096]
    const float* b1     = (const float*)d_in[4];   // [8,4096]
    const float* w2     = (const float*)d_in[5];   // [8,4096,1024]
    const float* b2     = (const float*)d_in[6];   // [8,1024]
    float* out = (float*)d_out;                    // combined [| loss | expert_load]

    init_kernel<<<(ROWS_MAX + 255) / 256, 256>>>();
    gate_kernel<<<(T_TOK * 32) / 256, 256>>>(x, gate_w, gate_b);
    finalize_gate_kernel<<<1, 32>>>(out, (long long)out_size);
    scatter_kernel<<<(T_TOK * TOPK + 255) / 256, 256>>>();

    // GEMM1: g_h = gelu(x_rows * W1[e] + b1[e]); K=1024, N=4096
    {
        dim3 grid(HID / BN, ROWS_MAX / BM);
        gemm_kernel<<<grid, 256>>>(x, w1, b1, DIM, HID, /*mode=*/1);
    }
    // GEMM2: g_o2 = g_h * W2[e]; K=4096, N=1024 (bias added in combine)
    {
        dim3 grid(DIM / BN, ROWS_MAX / BM);
        gemm_kernel<<<grid, 256>>>(x, w2, b2, HID, DIM, /*mode=*/2);
    }
    combine_kernel<<<(T_TOK * (DIM / 4) + 255) / 256, 256>>>(b2, out);
}

// round 6
// speedup vs baseline: 2.7326x; 2.7326x over previous
#include <cuda_runtime.h>
#include <cuda_bf16.h>
#include <math.h>
#include <stdint.h>

#define T_TOK   8192
#define DIM     1024
#define HID     4096
#define NEXP    8
#define TOPK    2

#define BM 128
#define BN 128
#define BK 32
#define STAGES 3
#define AP (BK + 8)        // padded A row (bf16)
#define BP (BN + 8)        // padded B row (bf16)
#define A_BYTES (BM * AP * 2)          // 10240
#define B_BYTES (BK * BP * 2)          // 8704
#define OFF_AHI 0
#define OFF_ALO (A_BYTES)
#define OFF_BHI (2 * A_BYTES)
#define OFF_BLO (2 * A_BYTES + B_BYTES)
#define SSTRIDE (2 * A_BYTES + 2 * B_BYTES)   // 37888
#define SM_HDR 1024
#define SMEM_TOTAL (SM_HDR + STAGES * SSTRIDE)  // 114688

#define ROWS_MAX 17408

// ---------------- device scratch (NEVER passed as kernel arguments!) ----------
__device__ __nv_bfloat16 g_w1hi[(size_t)NEXP * DIM * HID];
__device__ __nv_bfloat16 g_w1lo[(size_t)NEXP * DIM * HID];
__device__ __nv_bfloat16 g_w2hi[(size_t)NEXP * HID * DIM];
__device__ __nv_bfloat16 g_w2lo[(size_t)NEXP * HID * DIM];
__device__ __nv_bfloat16 g_xhi[(size_t)T_TOK * DIM];
__device__ __nv_bfloat16 g_xlo[(size_t)T_TOK * DIM];
__device__ __nv_bfloat16 g_hhi[(size_t)ROWS_MAX * HID];
__device__ __nv_bfloat16 g_hlo[(size_t)ROWS_MAX * HID];
__device__ float g_o2[(size_t)ROWS_MAX * DIM];
__device__ int   g_tok[ROWS_MAX];
__device__ int   g_row_of[T_TOK * TOPK];
__device__ int   g_topk[T_TOK * TOPK];
__device__ float g_probs[T_TOK * TOPK];
__device__ int   g_cnt[NEXP];
__device__ float g_loadf[NEXP];
__device__ int   g_off[NEXP + 1];
__device__ int   g_cursor[NEXP];

// ---------------- helpers ----------------
__device__ __forceinline__ uint32_t smem_u32(const void* p) {
    uint32_t a;
    asm("{ .reg .u64 t; cvta.to.shared.u64 t, %1; cvt.u32.u64 %0, t; }" : "=r"(a) : "l"(p));
    return a;
}
__device__ __forceinline__ void cp16(uint32_t dst, const void* src) {
    asm volatile("cp.async.cg.shared.global [%0], [%1], 16;" :: "r"(dst), "l"(src));
}
__device__ __forceinline__ void cp16z(uint32_t dst, const void* src, int sz) {
    asm volatile("cp.async.cg.shared.global [%0], [%1], 16, %2;" :: "r"(dst), "l"(src), "r"(sz));
}
#define CP_COMMIT() asm volatile("cp.async.commit_group;" ::: "memory")
#define CP_WAIT1()  asm volatile("cp.async.wait_group 1;" ::: "memory")

__device__ __forceinline__ void ldm_x4(uint32_t* r, uint32_t addr) {
    asm volatile("ldmatrix.sync.aligned.m8n8.x4.shared.b16 {%0,%1,%2,%3}, [%4];"
                 : "=r"(r[0]), "=r"(r[1]), "=r"(r[2]), "=r"(r[3]) : "r"(addr));
}
__device__ __forceinline__ void ldm_x4_t(uint32_t* r, uint32_t addr) {
    asm volatile("ldmatrix.sync.aligned.m8n8.x4.trans.shared.b16 {%0,%1,%2,%3}, [%4];"
                 : "=r"(r[0]), "=r"(r[1]), "=r"(r[2]), "=r"(r[3]) : "r"(addr));
}
__device__ __forceinline__ void mma_bf16(float* c, const uint32_t* a, const uint32_t* b) {
    asm volatile("mma.sync.aligned.m16n8k16.row.col.f32.bf16.bf16.f32 "
                 "{%0,%1,%2,%3}, {%4,%5,%6,%7}, {%8,%9}, {%0,%1,%2,%3};"
                 : "+f"(c[0]), "+f"(c[1]), "+f"(c[2]), "+f"(c[3])
                 : "r"(a[0]), "r"(a[1]), "r"(a[2]), "r"(a[3]), "r"(b[0]), "r"(b[1]));
}

// ---------------- small kernels ----------------
__global__ void init_kernel() {
    int i = blockIdx.x * blockDim.x + threadIdx.x;
    if (i < ROWS_MAX) g_tok[i] = -1;
    if (i < NEXP) { g_cnt[i] = 0; g_loadf[i] = 0.0f; }
}

__global__ void gate_kernel(const float* __restrict__ x,
                            const float* __restrict__ gw,
                            const float* __restrict__ gb) {
    int gtid = blockIdx.x * blockDim.x + threadIdx.x;
    int t = gtid >> 5, lane = gtid & 31;
    if (t >= T_TOK) return;
    const float* xr = x + (size_t)t * DIM;
    float acc[NEXP];
#pragma unroll
    for (int e = 0; e < NEXP; e++) acc[e] = 0.0f;
    for (int i = lane; i < DIM; i += 32) {
        float xv = xr[i];
        const float* g = gw + (size_t)i * NEXP;
#pragma unroll
        for (int e = 0; e < NEXP; e++) acc[e] = fmaf(xv, g[e], acc[e]);
    }
#pragma unroll
    for (int e = 0; e < NEXP; e++)
#pragma unroll
        for (int o = 16; o > 0; o >>= 1)
            acc[e] += __shfl_xor_sync(0xffffffffu, acc[e], o);
    if (lane == 0) {
        float l[NEXP];
#pragma unroll
        for (int e = 0; e < NEXP; e++) l[e] = acc[e] + gb[e];
        int i0 = 0;
#pragma unroll
        for (int e = 1; e < NEXP; e++) if (l[e] > l[i0]) i0 = e;
        int i1 = -1;
#pragma unroll
        for (int e = 0; e < NEXP; e++) {
            if (e == i0) continue;
            if (i1 < 0 || l[e] > l[i1]) i1 = e;
        }
        float e1 = expf(l[i1] - l[i0]);
        float s = 1.0f + e1;
        g_topk[2 * t] = i0;  g_topk[2 * t + 1] = i1;
        g_probs[2 * t] = 1.0f / s;  g_probs[2 * t + 1] = e1 / s;
        atomicAdd(&g_cnt[i0], 1);  atomicAdd(&g_cnt[i1], 1);
        atomicAdd(&g_loadf[i0], 1.0f / s);  atomicAdd(&g_loadf[i1], e1 / s);
    }
}

__global__ void finalize_gate_kernel(float* __restrict__ out, long long out_size) {
    if (threadIdx.x == 0 && blockIdx.x == 0) {
        int off = 0;
        for (int e = 0; e < NEXP; e++) {
            g_off[e] = off;  g_cursor[e] = off;
            off += ((g_cnt[e] + BM - 1) / BM) * BM;
        }
        g_off[NEXP] = off;
        if (out_size >= (long long)T_TOK * DIM + 1 + NEXP) {
            float* tail = out + (size_t)T_TOK * DIM;
            float loss = 0.0f;
            for (int e = 0; e < NEXP; e++) {
                float le = g_loadf[e] / (float)T_TOK;
                tail[1 + e] = le;
                float d = le - 1.0f / (float)NEXP;
                loss += d * d;
            }
            tail[0] = 0.01f * loss;
        }
    }
}

__global__ void scatter_kernel() {
    int i = blockIdx.x * blockDim.x + threadIdx.x;
    if (i >= T_TOK * TOPK) return;
    int e = g_topk[i];
    int r = atomicAdd(&g_cursor[e], 1);
    g_tok[r] = i >> 1;
    g_row_of[i] = r;
}

// fp32 -> bf16 hi/lo split; dst selected INTERNALLY by mode (0: x, 1: w1, 2: w2)
__global__ void split_kernel(const float* __restrict__ src, int mode, size_t n4) {
    size_t i = (size_t)blockIdx.x * blockDim.x + threadIdx.x;
    if (i >= n4) return;
    __nv_bfloat16* hi = (mode == 0) ? g_xhi : (mode == 1) ? g_w1hi : g_w2hi;
    __nv_bfloat16* lo = (mode == 0) ? g_xlo : (mode == 1) ? g_w1lo : g_w2lo;
    float4 v = ((const float4*)src)[i];
    __nv_bfloat16 h0 = __float2bfloat16(v.x), h1 = __float2bfloat16(v.y);
    __nv_bfloat16 h2 = __float2bfloat16(v.z), h3 = __float2bfloat16(v.w);
    float r0 = v.x - __bfloat162float(h0), r1 = v.y - __bfloat162float(h1);
    float r2 = v.z - __bfloat162float(h2), r3 = v.w - __bfloat162float(h3);
    uint2 ph, pl;
    ph.x = ((uint32_t)__bfloat16_as_ushort(h1) << 16) | __bfloat16_as_ushort(h0);
    ph.y = ((uint32_t)__bfloat16_as_ushort(h3) << 16) | __bfloat16_as_ushort(h2);
    pl.x = ((uint32_t)__bfloat16_as_ushort(__float2bfloat16(r1)) << 16) | __bfloat16_as_ushort(__float2bfloat16(r0));
    pl.y = ((uint32_t)__bfloat16_as_ushort(__float2bfloat16(r3)) << 16) | __bfloat16_as_ushort(__float2bfloat16(r2));
    ((uint2*)hi)[i] = ph;
    ((uint2*)lo)[i] = pl;
}

// ---------------- HMMA grouped GEMM ----------------
// mode 1: g_h = gelu(gather(x)[128,K] @ W1[e] + b1[e]);  K=DIM,  N=HID
// mode 2: g_o2 = g_h[128,K] @ W2[e];                      K=HID,  N=DIM
__global__ void __launch_bounds__(256)
moe_gemm_kernel(const float* __restrict__ bias, int K, int Ntot, int mode) {
    extern __shared__ __align__(1024) char smem[];
    int row0 = blockIdx.y * BM;
    if (row0 >= g_off[NEXP]) return;
    int col0 = blockIdx.x * BN;

    int tid = threadIdx.x;
    int wid = tid >> 5, lane = tid & 31;
    int wm = wid & 3, wn = wid >> 2;

    uint32_t sdata = smem_u32(smem) + SM_HDR;
    int* s_tok = (int*)smem;

    int e = 0;
#pragma unroll
    for (int i = 0; i < NEXP; i++) if (row0 >= g_off[i + 1]) e++;

    if (mode == 1 && tid < BM) s_tok[tid] = g_tok[row0 + tid];
    __syncthreads();

    const __nv_bfloat16* Whi = ((mode == 1) ? g_w1hi : g_w2hi) + (size_t)e * K * Ntot;
    const __nv_bfloat16* Wlo = ((mode == 1) ? g_w1lo : g_w2lo) + (size_t)e * K * Ntot;

    const int NC = K / BK;

    auto issue = [&](int c) {
        if (c < NC) {
            uint32_t sb = sdata + (c % STAGES) * SSTRIDE;
            int k0 = c * BK;
#pragma unroll
            for (int i = 0; i < 2; i++) {
                int j = i * 256 + tid;
                int ar = j >> 2, ac = (j & 3) * 8;
                uint32_t dA = sb + OFF_AHI + (uint32_t)(ar * AP + ac) * 2;
                if (mode == 1) {
                    int tk = s_tok[ar];
                    int sz = (tk >= 0) ? 16 : 0;
                    size_t so = (size_t)(tk >= 0 ? tk : 0) * DIM + k0 + ac;
                    cp16z(dA, g_xhi + so, sz);
                    cp16z(dA + A_BYTES, g_xlo + so, sz);
                } else {
                    size_t so = (size_t)(row0 + ar) * HID + k0 + ac;
                    cp16(dA, g_hhi + so);
                    cp16(dA + A_BYTES, g_hlo + so);
                }
            }
#pragma unroll
            for (int i = 0; i < 2; i++) {
                int j = i * 256 + tid;
                int br = j >> 4, bc = (j & 15) * 8;
                uint32_t dB = sb + OFF_BHI + (uint32_t)(br * BP + bc) * 2;
                size_t so = (size_t)(k0 + br) * Ntot + col0 + bc;
                cp16(dB, Whi + so);
                cp16(dB + B_BYTES, Wlo + so);
            }
        }
        CP_COMMIT();
    };

    float acc[2][8][4];
#pragma unroll
    for (int mf = 0; mf < 2; mf++)
#pragma unroll
        for (int nf = 0; nf < 8; nf++)
#pragma unroll
            for (int q = 0; q < 4; q++) acc[mf][nf][q] = 0.0f;

    issue(0);
    issue(1);

    for (int c = 0; c < NC; c++) {
        CP_WAIT1();
        __syncthreads();
        uint32_t sb = sdata + (c % STAGES) * SSTRIDE;

#pragma unroll
        for (int ks = 0; ks < 2; ks++) {
            uint32_t ah[2][4], al[2][4];
#pragma unroll
            for (int mf = 0; mf < 2; mf++) {
                uint32_t off = (uint32_t)((wm * 32 + mf * 16 + (lane & 15)) * AP
                                          + ks * 16 + (lane >> 4) * 8) * 2;
                ldm_x4(ah[mf], sb + OFF_AHI + off);
                ldm_x4(al[mf], sb + OFF_ALO + off);
            }
            uint32_t bh[8][2], bl[8][2];
#pragma unroll
            for (int ng = 0; ng < 4; ng++) {
                uint32_t off = (uint32_t)((ks * 16 + (lane & 15)) * BP
                                          + wn * 64 + ng * 16 + (lane >> 4) * 8) * 2;
                uint32_t r[4];
                ldm_x4_t(r, sb + OFF_BHI + off);
                bh[2 * ng][0] = r[0]; bh[2 * ng][1] = r[1];
                bh[2 * ng + 1][0] = r[2]; bh[2 * ng + 1][1] = r[3];
                ldm_x4_t(r, sb + OFF_BLO + off);
                bl[2 * ng][0] = r[0]; bl[2 * ng][1] = r[1];
                bl[2 * ng + 1][0] = r[2]; bl[2 * ng + 1][1] = r[3];
            }
#pragma unroll
            for (int mf = 0; mf < 2; mf++)
#pragma unroll
                for (int nf = 0; nf < 8; nf++) {
                    mma_bf16(acc[mf][nf], ah[mf], bh[nf]);
                    mma_bf16(acc[mf][nf], ah[mf], bl[nf]);
                    mma_bf16(acc[mf][nf], al[mf], bh[nf]);
                }
        }
        issue(c + 2);
    }

    // ---- epilogue ----
    int grow = lane >> 2;
    int gcol = (lane & 3) * 2;
    if (mode == 1) {
#pragma unroll
        for (int nf = 0; nf < 8; nf++) {
            int col = col0 + wn * 64 + nf * 8 + gcol;
            float b0 = bias[(size_t)e * Ntot + col];
            float b1 = bias[(size_t)e * Ntot + col + 1];
#pragma unroll
            for (int mf = 0; mf < 2; mf++) {
                int rb = row0 + wm * 32 + mf * 16 + grow;
#pragma unroll
                for (int h = 0; h < 2; h++) {
                    int r = rb + h * 8;
                    float v0 = acc[mf][nf][2 * h]     + b0;
                    float v1 = acc[mf][nf][2 * h + 1] + b1;
                    v0 = 0.5f * v0 * (1.0f + erff(v0 * 0.70710678118654752f));
                    v1 = 0.5f * v1 * (1.0f + erff(v1 * 0.70710678118654752f));
                    __nv_bfloat16 h0 = __float2bfloat16(v0), h1 = __float2bfloat16(v1);
                    float l0 = v0 - __bfloat162float(h0), l1 = v1 - __bfloat162float(h1);
                    uint32_t ph = ((uint32_t)__bfloat16_as_ushort(h1) << 16) | __bfloat16_as_ushort(h0);
                    uint32_t pl = ((uint32_t)__bfloat16_as_ushort(__float2bfloat16(l1)) << 16)
                                  | __bfloat16_as_ushort(__float2bfloat16(l0));
                    size_t o = (size_t)r * HID + col;
                    *(uint32_t*)(g_hhi + o) = ph;
                    *(uint32_t*)(g_hlo + o) = pl;
                }
            }
        }
    } else {
#pragma unroll
        for (int nf = 0; nf < 8; nf++) {
            int col = col0 + wn * 64 + nf * 8 + gcol;
#pragma unroll
            for (int mf = 0; mf < 2; mf++) {
                int rb = row0 + wm * 32 + mf * 16 + grow;
#pragma unroll
                for (int h = 0; h < 2; h++) {
                    int r = rb + h * 8;
                    float2 v = make_float2(acc[mf][nf][2 * h], acc[mf][nf][2 * h + 1]);
                    *(float2*)(g_o2 + (size_t)r * DIM + col) = v;
                }
            }
        }
    }
}

// ---------------- combine ----------------
__global__ void combine_kernel(const float* __restrict__ b2,
                               float* __restrict__ out) {
    int i4 = blockIdx.x * blockDim.x + threadIdx.x;
    const int D4 = DIM / 4;
    if (i4 >= T_TOK * D4) return;
    int t = i4 / D4;
    int d = (i4 - t * D4) * 4;
    int r0 = g_row_of[2 * t], r1 = g_row_of[2 * t + 1];
    int e0 = g_topk[2 * t],  e1 = g_topk[2 * t + 1];
    float p0 = g_probs[2 * t], p1 = g_probs[2 * t + 1];
    float4 a0 = *(const float4*)(g_o2 + (size_t)r0 * DIM + d);
    float4 a1 = *(const float4*)(g_o2 + (size_t)r1 * DIM + d);
    float4 c0 = *(const float4*)(b2 + (size_t)e0 * DIM + d);
    float4 c1 = *(const float4*)(b2 + (size_t)e1 * DIM + d);
    float4 o;
    o.x = p0 * (a0.x + c0.x) + p1 * (a1.x + c1.x);
    o.y = p0 * (a0.y + c0.y) + p1 * (a1.y + c1.y);
    o.z = p0 * (a0.z + c0.z) + p1 * (a1.z + c1.z);
    o.w = p0 * (a0.w + c0.w) + p1 * (a1.w + c1.w);
    *(float4*)(out + (size_t)t * DIM + d) = o;
}

// ---------------- launch ----------------
extern "C" void kernel_launch(void* const* d_in, const int* in_sizes, int n_in,
                              void* d_out, int out_size) {
    const float* x      = (const float*)d_in[0];
    const float* gate_w = (const float*)d_in[1];
    const float* gate_b = (const float*)d_in[2];
    const float* w1     = (const float*)d_in[3];
    const float* b1     = (const float*)d_in[4];
    const float* w2     = (const float*)d_in[5];
    const float* b2     = (const float*)d_in[6];
    float* out = (float*)d_out;

    cudaFuncSetAttribute(moe_gemm_kernel,
                         cudaFuncAttributeMaxDynamicSharedMemorySize, SMEM_TOTAL);

    init_kernel<<<(ROWS_MAX + 255) / 256, 256>>>();
    gate_kernel<<<(T_TOK * 32) / 256, 256>>>(x, gate_w, gate_b);
    finalize_gate_kernel<<<1, 32>>>(out, (long long)out_size);
    scatter_kernel<<<(T_TOK * TOPK + 255) / 256, 256>>>();

    {
        size_t n4 = (size_t)T_TOK * DIM / 4;
        split_kernel<<<(unsigned)((n4 + 255) / 256), 256>>>(x, 0, n4);
    }
    {
        size_t n4 = (size_t)NEXP * DIM * HID / 4;
        split_kernel<<<(unsigned)((n4 + 255) / 256), 256>>>(w1, 1, n4);
        split_kernel<<<(unsigned)((n4 + 255) / 256), 256>>>(w2, 2, n4);
    }

    // GEMM1: K=1024, N=4096
    {
        dim3 grid(HID / BN, ROWS_MAX / BM);
        moe_gemm_kernel<<<grid, 256, SMEM_TOTAL>>>(b1, DIM, HID, 1);
    }
    // GEMM2: K=4096, N=1024
    {
        dim3 grid(DIM / BN, ROWS_MAX / BM);
        moe_gemm_kernel<<<grid, 256, SMEM_TOTAL>>>(b2, HID, DIM, 2);
    }
    combine_kernel<<<(T_TOK * (DIM / 4) + 255) / 256, 256>>>(b2, out);
}

// round 7
// speedup vs baseline: 3.9947x; 1.4619x over previous
#include <cuda_runtime.h>
#include <cuda_fp16.h>
#include <math.h>
#include <stdint.h>

#define T_TOK   8192
#define DIM     1024
#define HID     4096
#define NEXP    8
#define TOPK    2

#define BM 128
#define BN 128
#define BK 64
#define STAGES 3
#define AP (BK + 8)                        // 72 fp16 per A row
#define BP (BN + 8)                        // 136 fp16 per B row
#define A_BYTES (BM * AP * 2)              // 18432
#define B_BYTES (BK * BP * 2)              // 17408
#define OFF_AHI 0
#define OFF_ALO (A_BYTES)
#define OFF_BH  (2 * A_BYTES)
#define SSTRIDE (2 * A_BYTES + B_BYTES)    // 54272
#define SM_HDR 1024
#define SMEM_TOTAL (SM_HDR + STAGES * SSTRIDE)   // 163840

#define ROWS_MAX 17408

// -------- device scratch (NEVER passed as kernel arguments — symbol-shadow bug) --------
__device__ __half g_w1h[(size_t)NEXP * DIM * HID];
__device__ __half g_w2h[(size_t)NEXP * HID * DIM];
__device__ __half g_xhi[(size_t)T_TOK * DIM];
__device__ __half g_xlo[(size_t)T_TOK * DIM];
__device__ __half g_hhi[(size_t)ROWS_MAX * HID];
__device__ __half g_hlo[(size_t)ROWS_MAX * HID];
__device__ float g_o2[(size_t)ROWS_MAX * DIM];
__device__ int   g_tok[ROWS_MAX];
__device__ int   g_row_of[T_TOK * TOPK];
__device__ int   g_topk[T_TOK * TOPK];
__device__ float g_probs[T_TOK * TOPK];
__device__ int   g_cnt[NEXP];
__device__ float g_loadf[NEXP];
__device__ int   g_off[NEXP + 1];
__device__ int   g_cursor[NEXP];

// ---------------- helpers ----------------
__device__ __forceinline__ uint32_t smem_u32(const void* p) {
    uint32_t a;
    asm("{ .reg .u64 t; cvta.to.shared.u64 t, %1; cvt.u32.u64 %0, t; }" : "=r"(a) : "l"(p));
    return a;
}
__device__ __forceinline__ void cp16(uint32_t dst, const void* src) {
    asm volatile("cp.async.cg.shared.global [%0], [%1], 16;" :: "r"(dst), "l"(src));
}
__device__ __forceinline__ void cp16z(uint32_t dst, const void* src, int sz) {
    asm volatile("cp.async.cg.shared.global [%0], [%1], 16, %2;" :: "r"(dst), "l"(src), "r"(sz));
}
#define CP_COMMIT() asm volatile("cp.async.commit_group;" ::: "memory")
#define CP_WAIT1()  asm volatile("cp.async.wait_group 1;" ::: "memory")

__device__ __forceinline__ void ldm_x4(uint32_t* r, uint32_t addr) {
    asm volatile("ldmatrix.sync.aligned.m8n8.x4.shared.b16 {%0,%1,%2,%3}, [%4];"
                 : "=r"(r[0]), "=r"(r[1]), "=r"(r[2]), "=r"(r[3]) : "r"(addr));
}
__device__ __forceinline__ void ldm_x4_t(uint32_t* r, uint32_t addr) {
    asm volatile("ldmatrix.sync.aligned.m8n8.x4.trans.shared.b16 {%0,%1,%2,%3}, [%4];"
                 : "=r"(r[0]), "=r"(r[1]), "=r"(r[2]), "=r"(r[3]) : "r"(addr));
}
__device__ __forceinline__ void mma_f16(float* c, const uint32_t* a, const uint32_t* b) {
    asm volatile("mma.sync.aligned.m16n8k16.row.col.f32.f16.f16.f32 "
                 "{%0,%1,%2,%3}, {%4,%5,%6,%7}, {%8,%9}, {%0,%1,%2,%3};"
                 : "+f"(c[0]), "+f"(c[1]), "+f"(c[2]), "+f"(c[3])
                 : "r"(a[0]), "r"(a[1]), "r"(a[2]), "r"(a[3]), "r"(b[0]), "r"(b[1]));
}

// ---------------- small kernels ----------------
__global__ void init_kernel() {
    int i = blockIdx.x * blockDim.x + threadIdx.x;
    if (i < ROWS_MAX) g_tok[i] = -1;
    if (i < NEXP) { g_cnt[i] = 0; g_loadf[i] = 0.0f; }
}

__global__ void gate_kernel(const float* __restrict__ x,
                            const float* __restrict__ gw,
                            const float* __restrict__ gb) {
    int gtid = blockIdx.x * blockDim.x + threadIdx.x;
    int t = gtid >> 5, lane = gtid & 31;
    if (t >= T_TOK) return;
    const float* xr = x + (size_t)t * DIM;
    float acc[NEXP];
#pragma unroll
    for (int e = 0; e < NEXP; e++) acc[e] = 0.0f;
    for (int i = lane; i < DIM; i += 32) {
        float xv = xr[i];
        const float* g = gw + (size_t)i * NEXP;
#pragma unroll
        for (int e = 0; e < NEXP; e++) acc[e] = fmaf(xv, g[e], acc[e]);
    }
#pragma unroll
    for (int e = 0; e < NEXP; e++)
#pragma unroll
        for (int o = 16; o > 0; o >>= 1)
            acc[e] += __shfl_xor_sync(0xffffffffu, acc[e], o);
    if (lane == 0) {
        float l[NEXP];
#pragma unroll
        for (int e = 0; e < NEXP; e++) l[e] = acc[e] + gb[e];
        int i0 = 0;
#pragma unroll
        for (int e = 1; e < NEXP; e++) if (l[e] > l[i0]) i0 = e;
        int i1 = -1;
#pragma unroll
        for (int e = 0; e < NEXP; e++) {
            if (e == i0) continue;
            if (i1 < 0 || l[e] > l[i1]) i1 = e;
        }
        float e1 = expf(l[i1] - l[i0]);
        float s = 1.0f + e1;
        g_topk[2 * t] = i0;  g_topk[2 * t + 1] = i1;
        g_probs[2 * t] = 1.0f / s;  g_probs[2 * t + 1] = e1 / s;
        atomicAdd(&g_cnt[i0], 1);  atomicAdd(&g_cnt[i1], 1);
        atomicAdd(&g_loadf[i0], 1.0f / s);  atomicAdd(&g_loadf[i1], e1 / s);
    }
}

__global__ void finalize_gate_kernel(float* __restrict__ out, long long out_size) {
    if (threadIdx.x == 0 && blockIdx.x == 0) {
        int off = 0;
        for (int e = 0; e < NEXP; e++) {
            g_off[e] = off;  g_cursor[e] = off;
            off += ((g_cnt[e] + BM - 1) / BM) * BM;
        }
        g_off[NEXP] = off;
        if (out_size >= (long long)T_TOK * DIM + 1 + NEXP) {
            float* tail = out + (size_t)T_TOK * DIM;
            float loss = 0.0f;
            for (int e = 0; e < NEXP; e++) {
                float le = g_loadf[e] / (float)T_TOK;
                tail[1 + e] = le;
                float d = le - 1.0f / (float)NEXP;
                loss += d * d;
            }
            tail[0] = 0.01f * loss;
        }
    }
}

__global__ void scatter_kernel() {
    int i = blockIdx.x * blockDim.x + threadIdx.x;
    if (i >= T_TOK * TOPK) return;
    int e = g_topk[i];
    int r = atomicAdd(&g_cursor[e], 1);
    g_tok[r] = i >> 1;
    g_row_of[i] = r;
}

// mode 0: x -> g_xhi + g_xlo (fp16 two-term split)
// mode 1: w1 -> g_w1h (fp16 round);  mode 2: w2 -> g_w2h
__global__ void split_kernel(const float* __restrict__ src, int mode, size_t n4) {
    size_t i = (size_t)blockIdx.x * blockDim.x + threadIdx.x;
    if (i >= n4) return;
    float4 v = ((const float4*)src)[i];
    __half h0 = __float2half_rn(v.x), h1 = __float2half_rn(v.y);
    __half h2 = __float2half_rn(v.z), h3 = __float2half_rn(v.w);
    uint2 ph;
    ph.x = ((uint32_t)__half_as_ushort(h1) << 16) | __half_as_ushort(h0);
    ph.y = ((uint32_t)__half_as_ushort(h3) << 16) | __half_as_ushort(h2);
    if (mode == 0) {
        float r0 = v.x - __half2float(h0), r1 = v.y - __half2float(h1);
        float r2 = v.z - __half2float(h2), r3 = v.w - __half2float(h3);
        uint2 pl;
        pl.x = ((uint32_t)__half_as_ushort(__float2half_rn(r1)) << 16) | __half_as_ushort(__float2half_rn(r0));
        pl.y = ((uint32_t)__half_as_ushort(__float2half_rn(r3)) << 16) | __half_as_ushort(__float2half_rn(r2));
        ((uint2*)g_xhi)[i] = ph;
        ((uint2*)g_xlo)[i] = pl;
    } else {
        __half* dst = (mode == 1) ? g_w1h : g_w2h;
        ((uint2*)dst)[i] = ph;
    }
}

// ---------------- HMMA grouped GEMM (fp16 2-pass) ----------------
// mode 1: g_h = gelu(gather(x)[128,K] @ W1[e] + b1[e]);  K=DIM,  N=HID
// mode 2: g_o2 = g_h[128,K] @ W2[e];                      K=HID,  N=DIM
__global__ void __launch_bounds__(256)
moe_gemm_kernel(const float* __restrict__ bias, int K, int Ntot, int mode) {
    extern __shared__ __align__(1024) char smem[];
    int row0 = blockIdx.y * BM;
    if (row0 >= g_off[NEXP]) return;
    int col0 = blockIdx.x * BN;

    int tid = threadIdx.x;
    int wid = tid >> 5, lane = tid & 31;
    int wm = wid & 3, wn = wid >> 2;

    uint32_t sdata = smem_u32(smem) + SM_HDR;
    int* s_tok = (int*)smem;

    int e = 0;
#pragma unroll
    for (int i = 0; i < NEXP; i++) if (row0 >= g_off[i + 1]) e++;

    if (mode == 1 && tid < BM) s_tok[tid] = g_tok[row0 + tid];
    __syncthreads();

    const __half* Wh = ((mode == 1) ? g_w1h : g_w2h) + (size_t)e * K * Ntot;

    const int NC = K / BK;

    auto issue = [&](int c) {
        if (c < NC) {
            uint32_t sb = sdata + (c % STAGES) * SSTRIDE;
            int k0 = c * BK;
            // A hi+lo: 128 rows x 64 fp16 = 1024 chunks of 16B each buffer
#pragma unroll
            for (int i = 0; i < 4; i++) {
                int j = i * 256 + tid;
                int ar = j >> 3, ac = (j & 7) * 8;
                uint32_t dA = sb + OFF_AHI + (uint32_t)(ar * AP + ac) * 2;
                if (mode == 1) {
                    int tk = s_tok[ar];
                    int sz = (tk >= 0) ? 16 : 0;
                    size_t so = (size_t)(tk >= 0 ? tk : 0) * DIM + k0 + ac;
                    cp16z(dA, g_xhi + so, sz);
                    cp16z(dA + A_BYTES, g_xlo + so, sz);
                } else {
                    size_t so = (size_t)(row0 + ar) * HID + k0 + ac;
                    cp16(dA, g_hhi + so);
                    cp16(dA + A_BYTES, g_hlo + so);
                }
            }
            // B hi: 64 rows x 128 fp16 = 1024 chunks
#pragma unroll
            for (int i = 0; i < 4; i++) {
                int j = i * 256 + tid;
                int br = j >> 4, bc = (j & 15) * 8;
                uint32_t dB = sb + OFF_BH + (uint32_t)(br * BP + bc) * 2;
                size_t so = (size_t)(k0 + br) * Ntot + col0 + bc;
                cp16(dB, Wh + so);
            }
        }
        CP_COMMIT();
    };

    float acc[2][8][4];
#pragma unroll
    for (int mf = 0; mf < 2; mf++)
#pragma unroll
        for (int nf = 0; nf < 8; nf++)
#pragma unroll
            for (int q = 0; q < 4; q++) acc[mf][nf][q] = 0.0f;

    issue(0);
    issue(1);

    for (int c = 0; c < NC; c++) {
        CP_WAIT1();
        __syncthreads();
        uint32_t sb = sdata + (c % STAGES) * SSTRIDE;

#pragma unroll
        for (int ks = 0; ks < 4; ks++) {
            uint32_t ah[2][4], al[2][4];
#pragma unroll
            for (int mf = 0; mf < 2; mf++) {
                uint32_t off = (uint32_t)((wm * 32 + mf * 16 + (lane & 15)) * AP
                                          + ks * 16 + (lane >> 4) * 8) * 2;
                ldm_x4(ah[mf], sb + OFF_AHI + off);
                ldm_x4(al[mf], sb + OFF_ALO + off);
            }
            uint32_t bh[8][2];
#pragma unroll
            for (int ng = 0; ng < 4; ng++) {
                uint32_t off = (uint32_t)((ks * 16 + (lane & 15)) * BP
                                          + wn * 64 + ng * 16 + (lane >> 4) * 8) * 2;
                uint32_t r[4];
                ldm_x4_t(r, sb + OFF_BH + off);
                bh[2 * ng][0] = r[0]; bh[2 * ng][1] = r[1];
                bh[2 * ng + 1][0] = r[2]; bh[2 * ng + 1][1] = r[3];
            }
#pragma unroll
            for (int mf = 0; mf < 2; mf++)
#pragma unroll
                for (int nf = 0; nf < 8; nf++) {
                    mma_f16(acc[mf][nf], ah[mf], bh[nf]);
                    mma_f16(acc[mf][nf], al[mf], bh[nf]);
                }
        }
        issue(c + 2);
    }

    // ---- epilogue ----
    int grow = lane >> 2;
    int gcol = (lane & 3) * 2;
    if (mode == 1) {
#pragma unroll
        for (int nf = 0; nf < 8; nf++) {
            int col = col0 + wn * 64 + nf * 8 + gcol;
            float b0 = bias[(size_t)e * Ntot + col];
            float b1 = bias[(size_t)e * Ntot + col + 1];
#pragma unroll
            for (int mf = 0; mf < 2; mf++) {
                int rb = row0 + wm * 32 + mf * 16 + grow;
#pragma unroll
                for (int h = 0; h < 2; h++) {
                    int r = rb + h * 8;
                    float v0 = acc[mf][nf][2 * h]     + b0;
                    float v1 = acc[mf][nf][2 * h + 1] + b1;
                    v0 = 0.5f * v0 * (1.0f + erff(v0 * 0.70710678118654752f));
                    v1 = 0.5f * v1 * (1.0f + erff(v1 * 0.70710678118654752f));
                    __half h0 = __float2half_rn(v0), h1 = __float2half_rn(v1);
                    float l0 = v0 - __half2float(h0), l1 = v1 - __half2float(h1);
                    uint32_t ph = ((uint32_t)__half_as_ushort(h1) << 16) | __half_as_ushort(h0);
                    uint32_t pl = ((uint32_t)__half_as_ushort(__float2half_rn(l1)) << 16)
                                  | __half_as_ushort(__float2half_rn(l0));
                    size_t o = (size_t)r * HID + col;
                    *(uint32_t*)(g_hhi + o) = ph;
                    *(uint32_t*)(g_hlo + o) = pl;
                }
            }
        }
    } else {
#pragma unroll
        for (int nf = 0; nf < 8; nf++) {
            int col = col0 + wn * 64 + nf * 8 + gcol;
#pragma unroll
            for (int mf = 0; mf < 2; mf++) {
                int rb = row0 + wm * 32 + mf * 16 + grow;
#pragma unroll
                for (int h = 0; h < 2; h++) {
                    int r = rb + h * 8;
                    float2 v = make_float2(acc[mf][nf][2 * h], acc[mf][nf][2 * h + 1]);
                    *(float2*)(g_o2 + (size_t)r * DIM + col) = v;
                }
            }
        }
    }
}

// ---------------- combine ----------------
__global__ void combine_kernel(const float* __restrict__ b2,
                               float* __restrict__ out) {
    int i4 = blockIdx.x * blockDim.x + threadIdx.x;
    const int D4 = DIM / 4;
    if (i4 >= T_TOK * D4) return;
    int t = i4 / D4;
    int d = (i4 - t * D4) * 4;
    int r0 = g_row_of[2 * t], r1 = g_row_of[2 * t + 1];
    int e0 = g_topk[2 * t],  e1 = g_topk[2 * t + 1];
    float p0 = g_probs[2 * t], p1 = g_probs[2 * t + 1];
    float4 a0 = *(const float4*)(g_o2 + (size_t)r0 * DIM + d);
    float4 a1 = *(const float4*)(g_o2 + (size_t)r1 * DIM + d);
    float4 c0 = *(const float4*)(b2 + (size_t)e0 * DIM + d);
    float4 c1 = *(const float4*)(b2 + (size_t)e1 * DIM + d);
    float4 o;
    o.x = p0 * (a0.x + c0.x) + p1 * (a1.x + c1.x);
    o.y = p0 * (a0.y + c0.y) + p1 * (a1.y + c1.y);
    o.z = p0 * (a0.z + c0.z) + p1 * (a1.z + c1.z);
    o.w = p0 * (a0.w + c0.w) + p1 * (a1.w + c1.w);
    *(float4*)(out + (size_t)t * DIM + d) = o;
}

// ---------------- launch ----------------
extern "C" void kernel_launch(void* const* d_in, const int* in_sizes, int n_in,
                              void* d_out, int out_size) {
    const float* x      = (const float*)d_in[0];
    const float* gate_w = (const float*)d_in[1];
    const float* gate_b = (const float*)d_in[2];
    const float* w1     = (const float*)d_in[3];
    const float* b1     = (const float*)d_in[4];
    const float* w2     = (const float*)d_in[5];
    const float* b2     = (const float*)d_in[6];
    float* out = (float*)d_out;

    cudaFuncSetAttribute(moe_gemm_kernel,
                         cudaFuncAttributeMaxDynamicSharedMemorySize, SMEM_TOTAL);

    init_kernel<<<(ROWS_MAX + 255) / 256, 256>>>();
    gate_kernel<<<(T_TOK * 32) / 256, 256>>>(x, gate_w, gate_b);
    finalize_gate_kernel<<<1, 32>>>(out, (long long)out_size);
    scatter_kernel<<<(T_TOK * TOPK + 255) / 256, 256>>>();

    {
        size_t n4 = (size_t)T_TOK * DIM / 4;
        split_kernel<<<(unsigned)((n4 + 255) / 256), 256>>>(x, 0, n4);
    }
    {
        size_t n4 = (size_t)NEXP * DIM * HID / 4;
        split_kernel<<<(unsigned)((n4 + 255) / 256), 256>>>(w1, 1, n4);
        split_kernel<<<(unsigned)((n4 + 255) / 256), 256>>>(w2, 2, n4);
    }

    // GEMM1: K=1024, N=4096
    {
        dim3 grid(HID / BN, ROWS_MAX / BM);
        moe_gemm_kernel<<<grid, 256, SMEM_TOTAL>>>(b1, DIM, HID, 1);
    }
    // GEMM2: K=4096, N=1024
    {
        dim3 grid(DIM / BN, ROWS_MAX / BM);
        moe_gemm_kernel<<<grid, 256, SMEM_TOTAL>>>(b2, HID, DIM, 2);
    }
    combine_kernel<<<(T_TOK * (DIM / 4) + 255) / 256, 256>>>(b2, out);
}

// round 8
// speedup vs baseline: 4.5279x; 1.1335x over previous
#include <cuda_runtime.h>
#include <cuda_fp16.h>
#include <math.h>
#include <stdint.h>

#define T_TOK   8192
#define DIM     1024
#define HID     4096
#define NEXP    8
#define TOPK    2

#define BM 128
#define BN 128
#define BK 32
#define STAGES 3
#define AP (BK + 8)                        // 40 fp16 per A row
#define BP (BN + 8)                        // 136 fp16 per B row
#define A_BYTES (BM * AP * 2)              // 10240
#define B_BYTES (BK * BP * 2)              // 8704
#define OFF_AHI 0
#define OFF_ALO (A_BYTES)
#define OFF_BH  (2 * A_BYTES)
#define SSTRIDE (2 * A_BYTES + B_BYTES)    // 29184
#define SM_HDR 1024
#define SMEM_TOTAL (SM_HDR + STAGES * SSTRIDE)   // 88576 -> 2 CTAs/SM

#define ROWS_MAX 17408

// -------- device scratch (NEVER passed as kernel arguments — symbol-shadow bug) --------
__device__ __half g_w1h[(size_t)NEXP * DIM * HID];
__device__ __half g_w2h[(size_t)NEXP * HID * DIM];
__device__ __half g_xhi[(size_t)T_TOK * DIM];
__device__ __half g_xlo[(size_t)T_TOK * DIM];
__device__ __half g_hhi[(size_t)ROWS_MAX * HID];
__device__ __half g_hlo[(size_t)ROWS_MAX * HID];
__device__ float g_o2[(size_t)ROWS_MAX * DIM];
__device__ int   g_tok[ROWS_MAX];
__device__ int   g_row_of[T_TOK * TOPK];
__device__ int   g_topk[T_TOK * TOPK];
__device__ float g_probs[T_TOK * TOPK];
__device__ int   g_cnt[NEXP];
__device__ float g_loadf[NEXP];
__device__ int   g_off[NEXP + 1];
__device__ int   g_cursor[NEXP];

// ---------------- helpers ----------------
__device__ __forceinline__ uint32_t smem_u32(const void* p) {
    uint32_t a;
    asm("{ .reg .u64 t; cvta.to.shared.u64 t, %1; cvt.u32.u64 %0, t; }" : "=r"(a) : "l"(p));
    return a;
}
__device__ __forceinline__ void cp16(uint32_t dst, const void* src) {
    asm volatile("cp.async.cg.shared.global [%0], [%1], 16;" :: "r"(dst), "l"(src));
}
__device__ __forceinline__ void cp16z(uint32_t dst, const void* src, int sz) {
    asm volatile("cp.async.cg.shared.global [%0], [%1], 16, %2;" :: "r"(dst), "l"(src), "r"(sz));
}
#define CP_COMMIT() asm volatile("cp.async.commit_group;" ::: "memory")
#define CP_WAIT1()  asm volatile("cp.async.wait_group 1;" ::: "memory")

__device__ __forceinline__ void ldm_x4(uint32_t* r, uint32_t addr) {
    asm volatile("ldmatrix.sync.aligned.m8n8.x4.shared.b16 {%0,%1,%2,%3}, [%4];"
                 : "=r"(r[0]), "=r"(r[1]), "=r"(r[2]), "=r"(r[3]) : "r"(addr));
}
__device__ __forceinline__ void ldm_x4_t(uint32_t* r, uint32_t addr) {
    asm volatile("ldmatrix.sync.aligned.m8n8.x4.trans.shared.b16 {%0,%1,%2,%3}, [%4];"
                 : "=r"(r[0]), "=r"(r[1]), "=r"(r[2]), "=r"(r[3]) : "r"(addr));
}
__device__ __forceinline__ void mma_f16(float* c, const uint32_t* a, const uint32_t* b) {
    asm volatile("mma.sync.aligned.m16n8k16.row.col.f32.f16.f16.f32 "
                 "{%0,%1,%2,%3}, {%4,%5,%6,%7}, {%8,%9}, {%0,%1,%2,%3};"
                 : "+f"(c[0]), "+f"(c[1]), "+f"(c[2]), "+f"(c[3])
                 : "r"(a[0]), "r"(a[1]), "r"(a[2]), "r"(a[3]), "r"(b[0]), "r"(b[1]));
}

// ---------------- small kernels ----------------
__global__ void init_kernel() {
    int i = blockIdx.x * blockDim.x + threadIdx.x;
    if (i < ROWS_MAX) g_tok[i] = -1;
    if (i < NEXP) { g_cnt[i] = 0; g_loadf[i] = 0.0f; }
}

__global__ void gate_kernel(const float* __restrict__ x,
                            const float* __restrict__ gw,
                            const float* __restrict__ gb) {
    int gtid = blockIdx.x * blockDim.x + threadIdx.x;
    int t = gtid >> 5, lane = gtid & 31;
    if (t >= T_TOK) return;
    const float* xr = x + (size_t)t * DIM;
    float acc[NEXP];
#pragma unroll
    for (int e = 0; e < NEXP; e++) acc[e] = 0.0f;
    for (int i = lane; i < DIM; i += 32) {
        float xv = xr[i];
        const float* g = gw + (size_t)i * NEXP;
#pragma unroll
        for (int e = 0; e < NEXP; e++) acc[e] = fmaf(xv, g[e], acc[e]);
    }
#pragma unroll
    for (int e = 0; e < NEXP; e++)
#pragma unroll
        for (int o = 16; o > 0; o >>= 1)
            acc[e] += __shfl_xor_sync(0xffffffffu, acc[e], o);
    if (lane == 0) {
        float l[NEXP];
#pragma unroll
        for (int e = 0; e < NEXP; e++) l[e] = acc[e] + gb[e];
        int i0 = 0;
#pragma unroll
        for (int e = 1; e < NEXP; e++) if (l[e] > l[i0]) i0 = e;
        int i1 = -1;
#pragma unroll
        for (int e = 0; e < NEXP; e++) {
            if (e == i0) continue;
            if (i1 < 0 || l[e] > l[i1]) i1 = e;
        }
        float e1 = expf(l[i1] - l[i0]);
        float s = 1.0f + e1;
        g_topk[2 * t] = i0;  g_topk[2 * t + 1] = i1;
        g_probs[2 * t] = 1.0f / s;  g_probs[2 * t + 1] = e1 / s;
        atomicAdd(&g_cnt[i0], 1);  atomicAdd(&g_cnt[i1], 1);
        atomicAdd(&g_loadf[i0], 1.0f / s);  atomicAdd(&g_loadf[i1], e1 / s);
    }
}

__global__ void finalize_gate_kernel(float* __restrict__ out, long long out_size) {
    if (threadIdx.x == 0 && blockIdx.x == 0) {
        int off = 0;
        for (int e = 0; e < NEXP; e++) {
            g_off[e] = off;  g_cursor[e] = off;
            off += ((g_cnt[e] + BM - 1) / BM) * BM;
        }
        g_off[NEXP] = off;
        if (out_size >= (long long)T_TOK * DIM + 1 + NEXP) {
            float* tail = out + (size_t)T_TOK * DIM;
            float loss = 0.0f;
            for (int e = 0; e < NEXP; e++) {
                float le = g_loadf[e] / (float)T_TOK;
                tail[1 + e] = le;
                float d = le - 1.0f / (float)NEXP;
                loss += d * d;
            }
            tail[0] = 0.01f * loss;
        }
    }
}

__global__ void scatter_kernel() {
    int i = blockIdx.x * blockDim.x + threadIdx.x;
    if (i >= T_TOK * TOPK) return;
    int e = g_topk[i];
    int r = atomicAdd(&g_cursor[e], 1);
    g_tok[r] = i >> 1;
    g_row_of[i] = r;
}

// ONE launch: x -> g_xhi/g_xlo (two-term), w1 -> g_w1h, w2 -> g_w2h (rounded)
#define X4  ((size_t)T_TOK * DIM / 4)
#define W4  ((size_t)NEXP * DIM * HID / 4)
__global__ void split_all_kernel(const float* __restrict__ x,
                                 const float* __restrict__ w1,
                                 const float* __restrict__ w2) {
    size_t i = (size_t)blockIdx.x * blockDim.x + threadIdx.x;
    if (i < X4) {
        float4 v = ((const float4*)x)[i];
        __half h0 = __float2half_rn(v.x), h1 = __float2half_rn(v.y);
        __half h2 = __float2half_rn(v.z), h3 = __float2half_rn(v.w);
        uint2 ph, pl;
        ph.x = ((uint32_t)__half_as_ushort(h1) << 16) | __half_as_ushort(h0);
        ph.y = ((uint32_t)__half_as_ushort(h3) << 16) | __half_as_ushort(h2);
        float r0 = v.x - __half2float(h0), r1 = v.y - __half2float(h1);
        float r2 = v.z - __half2float(h2), r3 = v.w - __half2float(h3);
        pl.x = ((uint32_t)__half_as_ushort(__float2half_rn(r1)) << 16) | __half_as_ushort(__float2half_rn(r0));
        pl.y = ((uint32_t)__half_as_ushort(__float2half_rn(r3)) << 16) | __half_as_ushort(__float2half_rn(r2));
        ((uint2*)g_xhi)[i] = ph;
        ((uint2*)g_xlo)[i] = pl;
    } else if (i < X4 + 2 * W4) {
        size_t j = i - X4;
        const float* src = (j < W4) ? w1 : w2;
        __half* dst = (j < W4) ? g_w1h : g_w2h;
        size_t k = (j < W4) ? j : j - W4;
        float4 v = ((const float4*)src)[k];
        uint2 ph;
        ph.x = ((uint32_t)__half_as_ushort(__float2half_rn(v.y)) << 16) | __half_as_ushort(__float2half_rn(v.x));
        ph.y = ((uint32_t)__half_as_ushort(__float2half_rn(v.w)) << 16) | __half_as_ushort(__float2half_rn(v.z));
        ((uint2*)dst)[k] = ph;
    }
}

// ---------------- HMMA grouped GEMM (fp16 2-pass, 2 CTA/SM) ----------------
__global__ void __launch_bounds__(256, 2)
moe_gemm_kernel(const float* __restrict__ bias, int K, int Ntot, int mode) {
    extern __shared__ __align__(1024) char smem[];
    int row0 = blockIdx.y * BM;
    if (row0 >= g_off[NEXP]) return;
    int col0 = blockIdx.x * BN;

    int tid = threadIdx.x;
    int wid = tid >> 5, lane = tid & 31;
    int wm = wid & 3, wn = wid >> 2;

    uint32_t sdata = smem_u32(smem) + SM_HDR;
    int* s_tok = (int*)smem;

    int e = 0;
#pragma unroll
    for (int i = 0; i < NEXP; i++) if (row0 >= g_off[i + 1]) e++;

    if (mode == 1 && tid < BM) s_tok[tid] = g_tok[row0 + tid];
    __syncthreads();

    const __half* Wh = ((mode == 1) ? g_w1h : g_w2h) + (size_t)e * K * Ntot;

    const int NC = K / BK;

    auto issue = [&](int c) {
        if (c < NC) {
            uint32_t sb = sdata + (c % STAGES) * SSTRIDE;
            int k0 = c * BK;
            // A hi+lo: 128 rows x 32 fp16 = 512 chunks of 16B per buffer
#pragma unroll
            for (int i = 0; i < 2; i++) {
                int j = i * 256 + tid;
                int ar = j >> 2, ac = (j & 3) * 8;
                uint32_t dA = sb + OFF_AHI + (uint32_t)(ar * AP + ac) * 2;
                if (mode == 1) {
                    int tk = s_tok[ar];
                    int sz = (tk >= 0) ? 16 : 0;
                    size_t so = (size_t)(tk >= 0 ? tk : 0) * DIM + k0 + ac;
                    cp16z(dA, g_xhi + so, sz);
                    cp16z(dA + A_BYTES, g_xlo + so, sz);
                } else {
                    size_t so = (size_t)(row0 + ar) * HID + k0 + ac;
                    cp16(dA, g_hhi + so);
                    cp16(dA + A_BYTES, g_hlo + so);
                }
            }
            // B: 32 rows x 128 fp16 = 512 chunks
#pragma unroll
            for (int i = 0; i < 2; i++) {
                int j = i * 256 + tid;
                int br = j >> 4, bc = (j & 15) * 8;
                uint32_t dB = sb + OFF_BH + (uint32_t)(br * BP + bc) * 2;
                size_t so = (size_t)(k0 + br) * Ntot + col0 + bc;
                cp16(dB, Wh + so);
            }
        }
        CP_COMMIT();
    };

    float acc[2][8][4];
#pragma unroll
    for (int mf = 0; mf < 2; mf++)
#pragma unroll
        for (int nf = 0; nf < 8; nf++)
#pragma unroll
            for (int q = 0; q < 4; q++) acc[mf][nf][q] = 0.0f;

    issue(0);
    issue(1);

    for (int c = 0; c < NC; c++) {
        CP_WAIT1();
        __syncthreads();
        uint32_t sb = sdata + (c % STAGES) * SSTRIDE;

#pragma unroll
        for (int ks = 0; ks < 2; ks++) {
            uint32_t ah[2][4], al[2][4];
#pragma unroll
            for (int mf = 0; mf < 2; mf++) {
                uint32_t off = (uint32_t)((wm * 32 + mf * 16 + (lane & 15)) * AP
                                          + ks * 16 + (lane >> 4) * 8) * 2;
                ldm_x4(ah[mf], sb + OFF_AHI + off);
                ldm_x4(al[mf], sb + OFF_ALO + off);
            }
            uint32_t bh[8][2];
#pragma unroll
            for (int ng = 0; ng < 4; ng++) {
                uint32_t off = (uint32_t)((ks * 16 + (lane & 15)) * BP
                                          + wn * 64 + ng * 16 + (lane >> 4) * 8) * 2;
                uint32_t r[4];
                ldm_x4_t(r, sb + OFF_BH + off);
                bh[2 * ng][0] = r[0]; bh[2 * ng][1] = r[1];
                bh[2 * ng + 1][0] = r[2]; bh[2 * ng + 1][1] = r[3];
            }
#pragma unroll
            for (int mf = 0; mf < 2; mf++)
#pragma unroll
                for (int nf = 0; nf < 8; nf++) {
                    mma_f16(acc[mf][nf], ah[mf], bh[nf]);
                    mma_f16(acc[mf][nf], al[mf], bh[nf]);
                }
        }
        issue(c + 2);
    }

    // ---- epilogue ----
    int grow = lane >> 2;
    int gcol = (lane & 3) * 2;
    if (mode == 1) {
#pragma unroll
        for (int nf = 0; nf < 8; nf++) {
            int col = col0 + wn * 64 + nf * 8 + gcol;
            float b0 = bias[(size_t)e * Ntot + col];
            float b1 = bias[(size_t)e * Ntot + col + 1];
#pragma unroll
            for (int mf = 0; mf < 2; mf++) {
                int rb = row0 + wm * 32 + mf * 16 + grow;
#pragma unroll
                for (int h = 0; h < 2; h++) {
                    int r = rb + h * 8;
                    float v0 = acc[mf][nf][2 * h]     + b0;
                    float v1 = acc[mf][nf][2 * h + 1] + b1;
                    v0 = 0.5f * v0 * (1.0f + erff(v0 * 0.70710678118654752f));
                    v1 = 0.5f * v1 * (1.0f + erff(v1 * 0.70710678118654752f));
                    __half h0 = __float2half_rn(v0), h1 = __float2half_rn(v1);
                    float l0 = v0 - __half2float(h0), l1 = v1 - __half2float(h1);
                    uint32_t ph = ((uint32_t)__half_as_ushort(h1) << 16) | __half_as_ushort(h0);
                    uint32_t pl = ((uint32_t)__half_as_ushort(__float2half_rn(l1)) << 16)
                                  | __half_as_ushort(__float2half_rn(l0));
                    size_t o = (size_t)r * HID + col;
                    *(uint32_t*)(g_hhi + o) = ph;
                    *(uint32_t*)(g_hlo + o) = pl;
                }
            }
        }
    } else {
#pragma unroll
        for (int nf = 0; nf < 8; nf++) {
            int col = col0 + wn * 64 + nf * 8 + gcol;
#pragma unroll
            for (int mf = 0; mf < 2; mf++) {
                int rb = row0 + wm * 32 + mf * 16 + grow;
#pragma unroll
                for (int h = 0; h < 2; h++) {
                    int r = rb + h * 8;
                    float2 v = make_float2(acc[mf][nf][2 * h], acc[mf][nf][2 * h + 1]);
                    *(float2*)(g_o2 + (size_t)r * DIM + col) = v;
                }
            }
        }
    }
}

// ---------------- combine ----------------
__global__ void combine_kernel(const float* __restrict__ b2,
                               float* __restrict__ out) {
    int i4 = blockIdx.x * blockDim.x + threadIdx.x;
    const int D4 = DIM / 4;
    if (i4 >= T_TOK * D4) return;
    int t = i4 / D4;
    int d = (i4 - t * D4) * 4;
    int r0 = g_row_of[2 * t], r1 = g_row_of[2 * t + 1];
    int e0 = g_topk[2 * t],  e1 = g_topk[2 * t + 1];
    float p0 = g_probs[2 * t], p1 = g_probs[2 * t + 1];
    float4 a0 = *(const float4*)(g_o2 + (size_t)r0 * DIM + d);
    float4 a1 = *(const float4*)(g_o2 + (size_t)r1 * DIM + d);
    float4 c0 = *(const float4*)(b2 + (size_t)e0 * DIM + d);
    float4 c1 = *(const float4*)(b2 + (size_t)e1 * DIM + d);
    float4 o;
    o.x = p0 * (a0.x + c0.x) + p1 * (a1.x + c1.x);
    o.y = p0 * (a0.y + c0.y) + p1 * (a1.y + c1.y);
    o.z = p0 * (a0.z + c0.z) + p1 * (a1.z + c1.z);
    o.w = p0 * (a0.w + c0.w) + p1 * (a1.w + c1.w);
    *(float4*)(out + (size_t)t * DIM + d) = o;
}

// ---------------- launch ----------------
extern "C" void kernel_launch(void* const* d_in, const int* in_sizes, int n_in,
                              void* d_out, int out_size) {
    const float* x      = (const float*)d_in[0];
    const float* gate_w = (const float*)d_in[1];
    const float* gate_b = (const float*)d_in[2];
    const float* w1     = (const float*)d_in[3];
    const float* b1     = (const float*)d_in[4];
    const float* w2     = (const float*)d_in[5];
    const float* b2     = (const float*)d_in[6];
    float* out = (float*)d_out;

    cudaFuncSetAttribute(moe_gemm_kernel,
                         cudaFuncAttributeMaxDynamicSharedMemorySize, SMEM_TOTAL);

    // launch order matters for ncu (-s 5 -c 1): gemm1 is launch index 5
    init_kernel<<<(ROWS_MAX + 255) / 256, 256>>>();                         // 0
    gate_kernel<<<(T_TOK * 32) / 256, 256>>>(x, gate_w, gate_b);            // 1
    finalize_gate_kernel<<<1, 32>>>(out, (long long)out_size);              // 2
    scatter_kernel<<<(T_TOK * TOPK + 255) / 256, 256>>>();                  // 3
    {
        size_t total = X4 + 2 * W4;
        split_all_kernel<<<(unsigned)((total + 255) / 256), 256>>>(x, w1, w2); // 4
    }
    {
        dim3 grid(HID / BN, ROWS_MAX / BM);
        moe_gemm_kernel<<<grid, 256, SMEM_TOTAL>>>(b1, DIM, HID, 1);        // 5  <- ncu
    }
    {
        dim3 grid(DIM / BN, ROWS_MAX / BM);
        moe_gemm_kernel<<<grid, 256, SMEM_TOTAL>>>(b2, HID, DIM, 2);        // 6
    }
    combine_kernel<<<(T_TOK * (DIM / 4) + 255) / 256, 256>>>(b2, out);      // 7
}

// round 9
// speedup vs baseline: 7.5231x; 1.6615x over previous
#include <cuda_runtime.h>
#include <cuda_fp16.h>
#include <math.h>
#include <stdint.h>

#define T_TOK   8192
#define DIM     1024
#define HID     4096
#define NEXP    8
#define TOPK    2

#define BM 128
#define BN 128
#define BK 32
#define STAGES 4
#define AP (BK + 8)                        // 40 fp16 per A row
#define BP (BN + 8)                        // 136 fp16 per B row
#define A_BYTES (BM * AP * 2)              // 10240
#define B_BYTES (BK * BP * 2)              // 8704
#define OFF_A 0
#define OFF_B (A_BYTES)
#define SSTRIDE (A_BYTES + B_BYTES)        // 18944
#define SM_HDR 1024
#define SMEM_TOTAL (SM_HDR + STAGES * SSTRIDE)   // 76800 -> 2 CTAs/SM

#define ROWS_MAX 17408

// -------- device scratch (NEVER passed as kernel arguments — symbol-shadow bug) --------
__device__ __half g_w1h[(size_t)NEXP * DIM * HID];
__device__ __half g_w2h[(size_t)NEXP * HID * DIM];
__device__ __half g_xh[(size_t)T_TOK * DIM];
__device__ __half g_hh[(size_t)ROWS_MAX * HID];
__device__ float g_o2[(size_t)ROWS_MAX * DIM];
__device__ int   g_tok[ROWS_MAX];
__device__ int   g_row_of[T_TOK * TOPK];
__device__ int   g_topk[T_TOK * TOPK];
__device__ float g_probs[T_TOK * TOPK];
__device__ int   g_cnt[NEXP];
__device__ float g_loadf[NEXP];
__device__ int   g_off[NEXP + 1];
__device__ int   g_cursor[NEXP];

// ---------------- helpers ----------------
__device__ __forceinline__ uint32_t smem_u32(const void* p) {
    uint32_t a;
    asm("{ .reg .u64 t; cvta.to.shared.u64 t, %1; cvt.u32.u64 %0, t; }" : "=r"(a) : "l"(p));
    return a;
}
__device__ __forceinline__ void cp16(uint32_t dst, const void* src) {
    asm volatile("cp.async.cg.shared.global [%0], [%1], 16;" :: "r"(dst), "l"(src));
}
__device__ __forceinline__ void cp16z(uint32_t dst, const void* src, int sz) {
    asm volatile("cp.async.cg.shared.global [%0], [%1], 16, %2;" :: "r"(dst), "l"(src), "r"(sz));
}
#define CP_COMMIT() asm volatile("cp.async.commit_group;" ::: "memory")
#define CP_WAIT2()  asm volatile("cp.async.wait_group 2;" ::: "memory")

__device__ __forceinline__ void ldm_x4(uint32_t* r, uint32_t addr) {
    asm volatile("ldmatrix.sync.aligned.m8n8.x4.shared.b16 {%0,%1,%2,%3}, [%4];"
                 : "=r"(r[0]), "=r"(r[1]), "=r"(r[2]), "=r"(r[3]) : "r"(addr));
}
__device__ __forceinline__ void ldm_x4_t(uint32_t* r, uint32_t addr) {
    asm volatile("ldmatrix.sync.aligned.m8n8.x4.trans.shared.b16 {%0,%1,%2,%3}, [%4];"
                 : "=r"(r[0]), "=r"(r[1]), "=r"(r[2]), "=r"(r[3]) : "r"(addr));
}
__device__ __forceinline__ void mma_f16(float* c, const uint32_t* a, const uint32_t* b) {
    asm volatile("mma.sync.aligned.m16n8k16.row.col.f32.f16.f16.f32 "
                 "{%0,%1,%2,%3}, {%4,%5,%6,%7}, {%8,%9}, {%0,%1,%2,%3};"
                 : "+f"(c[0]), "+f"(c[1]), "+f"(c[2]), "+f"(c[3])
                 : "r"(a[0]), "r"(a[1]), "r"(a[2]), "r"(a[3]), "r"(b[0]), "r"(b[1]));
}

// ---------------- small kernels ----------------
__global__ void init_kernel() {
    int i = blockIdx.x * blockDim.x + threadIdx.x;
    if (i < ROWS_MAX) g_tok[i] = -1;
    if (i < NEXP) { g_cnt[i] = 0; g_loadf[i] = 0.0f; }
}

__global__ void gate_kernel(const float* __restrict__ x,
                            const float* __restrict__ gw,
                            const float* __restrict__ gb) {
    int gtid = blockIdx.x * blockDim.x + threadIdx.x;
    int t = gtid >> 5, lane = gtid & 31;
    if (t >= T_TOK) return;
    const float* xr = x + (size_t)t * DIM;
    float acc[NEXP];
#pragma unroll
    for (int e = 0; e < NEXP; e++) acc[e] = 0.0f;
    for (int i = lane; i < DIM; i += 32) {
        float xv = xr[i];
        const float* g = gw + (size_t)i * NEXP;
#pragma unroll
        for (int e = 0; e < NEXP; e++) acc[e] = fmaf(xv, g[e], acc[e]);
    }
#pragma unroll
    for (int e = 0; e < NEXP; e++)
#pragma unroll
        for (int o = 16; o > 0; o >>= 1)
            acc[e] += __shfl_xor_sync(0xffffffffu, acc[e], o);
    if (lane == 0) {
        float l[NEXP];
#pragma unroll
        for (int e = 0; e < NEXP; e++) l[e] = acc[e] + gb[e];
        int i0 = 0;
#pragma unroll
        for (int e = 1; e < NEXP; e++) if (l[e] > l[i0]) i0 = e;
        int i1 = -1;
#pragma unroll
        for (int e = 0; e < NEXP; e++) {
            if (e == i0) continue;
            if (i1 < 0 || l[e] > l[i1]) i1 = e;
        }
        float e1 = expf(l[i1] - l[i0]);
        float s = 1.0f + e1;
        g_topk[2 * t] = i0;  g_topk[2 * t + 1] = i1;
        g_probs[2 * t] = 1.0f / s;  g_probs[2 * t + 1] = e1 / s;
        atomicAdd(&g_cnt[i0], 1);  atomicAdd(&g_cnt[i1], 1);
        atomicAdd(&g_loadf[i0], 1.0f / s);  atomicAdd(&g_loadf[i1], e1 / s);
    }
}

__global__ void finalize_gate_kernel(float* __restrict__ out, long long out_size) {
    if (threadIdx.x == 0 && blockIdx.x == 0) {
        int off = 0;
        for (int e = 0; e < NEXP; e++) {
            g_off[e] = off;  g_cursor[e] = off;
            off += ((g_cnt[e] + BM - 1) / BM) * BM;
        }
        g_off[NEXP] = off;
        if (out_size >= (long long)T_TOK * DIM + 1 + NEXP) {
            float* tail = out + (size_t)T_TOK * DIM;
            float loss = 0.0f;
            for (int e = 0; e < NEXP; e++) {
                float le = g_loadf[e] / (float)T_TOK;
                tail[1 + e] = le;
                float d = le - 1.0f / (float)NEXP;
                loss += d * d;
            }
            tail[0] = 0.01f * loss;
        }
    }
}

__global__ void scatter_kernel() {
    int i = blockIdx.x * blockDim.x + threadIdx.x;
    if (i >= T_TOK * TOPK) return;
    int e = g_topk[i];
    int r = atomicAdd(&g_cursor[e], 1);
    g_tok[r] = i >> 1;
    g_row_of[i] = r;
}

// ONE launch: x -> g_xh, w1 -> g_w1h, w2 -> g_w2h (fp16 round)
#define X4  ((size_t)T_TOK * DIM / 4)
#define W4  ((size_t)NEXP * DIM * HID / 4)
__global__ void split_all_kernel(const float* __restrict__ x,
                                 const float* __restrict__ w1,
                                 const float* __restrict__ w2) {
    size_t i = (size_t)blockIdx.x * blockDim.x + threadIdx.x;
    if (i >= X4 + 2 * W4) return;
    const float* src;
    __half* dst;
    size_t k;
    if (i < X4)            { src = x;  dst = g_xh;  k = i; }
    else if (i < X4 + W4)  { src = w1; dst = g_w1h; k = i - X4; }
    else                   { src = w2; dst = g_w2h; k = i - X4 - W4; }
    float4 v = ((const float4*)src)[k];
    uint2 ph;
    ph.x = ((uint32_t)__half_as_ushort(__float2half_rn(v.y)) << 16) | __half_as_ushort(__float2half_rn(v.x));
    ph.y = ((uint32_t)__half_as_ushort(__float2half_rn(v.w)) << 16) | __half_as_ushort(__float2half_rn(v.z));
    ((uint2*)dst)[k] = ph;
}

// ---------------- HMMA grouped GEMM (fp16 single-pass, 4-stage, 2 CTA/SM) ----------
__global__ void __launch_bounds__(256, 2)
moe_gemm_kernel(const float* __restrict__ bias, int K, int Ntot, int mode) {
    extern __shared__ __align__(1024) char smem[];
    int row0 = blockIdx.y * BM;
    if (row0 >= g_off[NEXP]) return;
    int col0 = blockIdx.x * BN;

    int tid = threadIdx.x;
    int wid = tid >> 5, lane = tid & 31;
    int wm = wid & 3, wn = wid >> 2;

    uint32_t sdata = smem_u32(smem) + SM_HDR;
    int* s_tok = (int*)smem;

    int e = 0;
#pragma unroll
    for (int i = 0; i < NEXP; i++) if (row0 >= g_off[i + 1]) e++;

    if (mode == 1 && tid < BM) s_tok[tid] = g_tok[row0 + tid];
    __syncthreads();

    const __half* Wh = ((mode == 1) ? g_w1h : g_w2h) + (size_t)e * K * Ntot;

    const int NC = K / BK;

    auto issue = [&](int c) {
        if (c < NC) {
            uint32_t sb = sdata + (c % STAGES) * SSTRIDE;
            int k0 = c * BK;
            // A: 128 rows x 32 fp16 = 512 chunks of 16B
#pragma unroll
            for (int i = 0; i < 2; i++) {
                int j = i * 256 + tid;
                int ar = j >> 2, ac = (j & 3) * 8;
                uint32_t dA = sb + OFF_A + (uint32_t)(ar * AP + ac) * 2;
                if (mode == 1) {
                    int tk = s_tok[ar];
                    int sz = (tk >= 0) ? 16 : 0;
                    size_t so = (size_t)(tk >= 0 ? tk : 0) * DIM + k0 + ac;
                    cp16z(dA, g_xh + so, sz);
                } else {
                    cp16(dA, g_hh + (size_t)(row0 + ar) * HID + k0 + ac);
                }
            }
            // B: 32 rows x 128 fp16 = 512 chunks
#pragma unroll
            for (int i = 0; i < 2; i++) {
                int j = i * 256 + tid;
                int br = j >> 4, bc = (j & 15) * 8;
                uint32_t dB = sb + OFF_B + (uint32_t)(br * BP + bc) * 2;
                cp16(dB, Wh + (size_t)(k0 + br) * Ntot + col0 + bc);
            }
        }
        CP_COMMIT();
    };

    float acc[2][8][4];
#pragma unroll
    for (int mf = 0; mf < 2; mf++)
#pragma unroll
        for (int nf = 0; nf < 8; nf++)
#pragma unroll
            for (int q = 0; q < 4; q++) acc[mf][nf][q] = 0.0f;

    issue(0);
    issue(1);
    issue(2);

    for (int c = 0; c < NC; c++) {
        CP_WAIT2();
        __syncthreads();
        uint32_t sb = sdata + (c % STAGES) * SSTRIDE;

#pragma unroll
        for (int ks = 0; ks < 2; ks++) {
            uint32_t ah[2][4];
#pragma unroll
            for (int mf = 0; mf < 2; mf++) {
                uint32_t off = (uint32_t)((wm * 32 + mf * 16 + (lane & 15)) * AP
                                          + ks * 16 + (lane >> 4) * 8) * 2;
                ldm_x4(ah[mf], sb + OFF_A + off);
            }
            uint32_t bh[8][2];
#pragma unroll
            for (int ng = 0; ng < 4; ng++) {
                uint32_t off = (uint32_t)((ks * 16 + (lane & 15)) * BP
                                          + wn * 64 + ng * 16 + (lane >> 4) * 8) * 2;
                uint32_t r[4];
                ldm_x4_t(r, sb + OFF_B + off);
                bh[2 * ng][0] = r[0]; bh[2 * ng][1] = r[1];
                bh[2 * ng + 1][0] = r[2]; bh[2 * ng + 1][1] = r[3];
            }
#pragma unroll
            for (int mf = 0; mf < 2; mf++)
#pragma unroll
                for (int nf = 0; nf < 8; nf++)
                    mma_f16(acc[mf][nf], ah[mf], bh[nf]);
        }
        issue(c + 3);
    }

    // ---- epilogue ----
    int grow = lane >> 2;
    int gcol = (lane & 3) * 2;
    if (mode == 1) {
#pragma unroll
        for (int nf = 0; nf < 8; nf++) {
            int col = col0 + wn * 64 + nf * 8 + gcol;
            float b0 = bias[(size_t)e * Ntot + col];
            float b1 = bias[(size_t)e * Ntot + col + 1];
#pragma unroll
            for (int mf = 0; mf < 2; mf++) {
                int rb = row0 + wm * 32 + mf * 16 + grow;
#pragma unroll
                for (int h = 0; h < 2; h++) {
                    int r = rb + h * 8;
                    float v0 = acc[mf][nf][2 * h]     + b0;
                    float v1 = acc[mf][nf][2 * h + 1] + b1;
                    v0 = 0.5f * v0 * (1.0f + erff(v0 * 0.70710678118654752f));
                    v1 = 0.5f * v1 * (1.0f + erff(v1 * 0.70710678118654752f));
                    uint32_t ph = ((uint32_t)__half_as_ushort(__float2half_rn(v1)) << 16)
                                  | __half_as_ushort(__float2half_rn(v0));
                    *(uint32_t*)(g_hh + (size_t)r * HID + col) = ph;
                }
            }
        }
    } else {
#pragma unroll
        for (int nf = 0; nf < 8; nf++) {
            int col = col0 + wn * 64 + nf * 8 + gcol;
#pragma unroll
            for (int mf = 0; mf < 2; mf++) {
                int rb = row0 + wm * 32 + mf * 16 + grow;
#pragma unroll
                for (int h = 0; h < 2; h++) {
                    int r = rb + h * 8;
                    float2 v = make_float2(acc[mf][nf][2 * h], acc[mf][nf][2 * h + 1]);
                    *(float2*)(g_o2 + (size_t)r * DIM + col) = v;
                }
            }
        }
    }
}

// ---------------- combine ----------------
__global__ void combine_kernel(const float* __restrict__ b2,
                               float* __restrict__ out) {
    int i4 = blockIdx.x * blockDim.x + threadIdx.x;
    const int D4 = DIM / 4;
    if (i4 >= T_TOK * D4) return;
    int t = i4 / D4;
    int d = (i4 - t * D4) * 4;
    int r0 = g_row_of[2 * t], r1 = g_row_of[2 * t + 1];
    int e0 = g_topk[2 * t],  e1 = g_topk[2 * t + 1];
    float p0 = g_probs[2 * t], p1 = g_probs[2 * t + 1];
    float4 a0 = *(const float4*)(g_o2 + (size_t)r0 * DIM + d);
    float4 a1 = *(const float4*)(g_o2 + (size_t)r1 * DIM + d);
    float4 c0 = *(const float4*)(b2 + (size_t)e0 * DIM + d);
    float4 c1 = *(const float4*)(b2 + (size_t)e1 * DIM + d);
    float4 o;
    o.x = p0 * (a0.x + c0.x) + p1 * (a1.x + c1.x);
    o.y = p0 * (a0.y + c0.y) + p1 * (a1.y + c1.y);
    o.z = p0 * (a0.z + c0.z) + p1 * (a1.z + c1.z);
    o.w = p0 * (a0.w + c0.w) + p1 * (a1.w + c1.w);
    *(float4*)(out + (size_t)t * DIM + d) = o;
}

// ---------------- launch ----------------
extern "C" void kernel_launch(void* const* d_in, const int* in_sizes, int n_in,
                              void* d_out, int out_size) {
    const float* x      = (const float*)d_in[0];
    const float* gate_w = (const float*)d_in[1];
    const float* gate_b = (const float*)d_in[2];
    const float* w1     = (const float*)d_in[3];
    const float* b1     = (const float*)d_in[4];
    const float* w2     = (const float*)d_in[5];
    const float* b2     = (const float*)d_in[6];
    float* out = (float*)d_out;

    cudaFuncSetAttribute(moe_gemm_kernel,
                         cudaFuncAttributeMaxDynamicSharedMemorySize, SMEM_TOTAL);

    init_kernel<<<(ROWS_MAX + 255) / 256, 256>>>();
    gate_kernel<<<(T_TOK * 32) / 256, 256>>>(x, gate_w, gate_b);
    finalize_gate_kernel<<<1, 32>>>(out, (long long)out_size);
    scatter_kernel<<<(T_TOK * TOPK + 255) / 256, 256>>>();
    {
        size_t total = X4 + 2 * W4;
        split_all_kernel<<<(unsigned)((total + 255) / 256), 256>>>(x, w1, w2);
    }
    {
        dim3 grid(HID / BN, ROWS_MAX / BM);
        moe_gemm_kernel<<<grid, 256, SMEM_TOTAL>>>(b1, DIM, HID, 1);
    }
    {
        dim3 grid(DIM / BN, ROWS_MAX / BM);
        moe_gemm_kernel<<<grid, 256, SMEM_TOTAL>>>(b2, HID, DIM, 2);
    }
    combine_kernel<<<(T_TOK * (DIM / 4) + 255) / 256, 256>>>(b2, out);
}

// round 13
// speedup vs baseline: 7.5394x; 1.0022x over previous
#include <cuda_runtime.h>
#include <cuda_fp16.h>
#include <math.h>
#include <stdint.h>

#define T_TOK   8192
#define DIM     1024
#define HID     4096
#define NEXP    8
#define TOPK    2

#define BM 128
#define BN 128
#define BK 64
#define STAGES 3
#define AP (BK + 8)                        // 72 fp16 per A row
#define BP (BN + 8)                        // 136 fp16 per B row
#define A_BYTES (BM * AP * 2)              // 18432
#define B_BYTES (BK * BP * 2)              // 17408
#define OFF_A 0
#define OFF_B (A_BYTES)
#define SSTRIDE (A_BYTES + B_BYTES)        // 35840
#define SM_HDR 1024
#define SMEM_TOTAL (SM_HDR + STAGES * SSTRIDE)   // 108544 -> 2 CTAs/SM (217KB)

#define ROWS_MAX 17408

// -------- device scratch (NEVER passed as kernel arguments — symbol-shadow bug) --------
__device__ __half g_w1h[(size_t)NEXP * DIM * HID];
__device__ __half g_w2h[(size_t)NEXP * HID * DIM];
__device__ __half g_xh[(size_t)T_TOK * DIM];
__device__ __half g_hh[(size_t)ROWS_MAX * HID];
__device__ float g_o2[(size_t)ROWS_MAX * DIM];
__device__ int   g_tok[ROWS_MAX];
__device__ int   g_row_of[T_TOK * TOPK];
__device__ int   g_topk[T_TOK * TOPK];
__device__ float g_probs[T_TOK * TOPK];
__device__ int   g_cnt[NEXP];
__device__ float g_loadf[NEXP];
__device__ int   g_off[NEXP + 1];
__device__ int   g_cursor[NEXP];

// ---------------- helpers ----------------
__device__ __forceinline__ uint32_t smem_u32(const void* p) {
    uint32_t a;
    asm("{ .reg .u64 t; cvta.to.shared.u64 t, %1; cvt.u32.u64 %0, t; }" : "=r"(a) : "l"(p));
    return a;
}
__device__ __forceinline__ void cp16(uint32_t dst, const void* src) {
    asm volatile("cp.async.cg.shared.global [%0], [%1], 16;" :: "r"(dst), "l"(src));
}
__device__ __forceinline__ void cp16z(uint32_t dst, const void* src, int sz) {
    asm volatile("cp.async.cg.shared.global [%0], [%1], 16, %2;" :: "r"(dst), "l"(src), "r"(sz));
}
#define CP_COMMIT() asm volatile("cp.async.commit_group;" ::: "memory")
#define CP_WAIT1()  asm volatile("cp.async.wait_group 1;" ::: "memory")

__device__ __forceinline__ void ldm_x4(uint32_t* r, uint32_t addr) {
    asm volatile("ldmatrix.sync.aligned.m8n8.x4.shared.b16 {%0,%1,%2,%3}, [%4];"
                 : "=r"(r[0]), "=r"(r[1]), "=r"(r[2]), "=r"(r[3]) : "r"(addr));
}
__device__ __forceinline__ void ldm_x4_t(uint32_t* r, uint32_t addr) {
    asm volatile("ldmatrix.sync.aligned.m8n8.x4.trans.shared.b16 {%0,%1,%2,%3}, [%4];"
                 : "=r"(r[0]), "=r"(r[1]), "=r"(r[2]), "=r"(r[3]) : "r"(addr));
}
__device__ __forceinline__ void mma_f16(float* c, const uint32_t* a, const uint32_t* b) {
    asm volatile("mma.sync.aligned.m16n8k16.row.col.f32.f16.f16.f32 "
                 "{%0,%1,%2,%3}, {%4,%5,%6,%7}, {%8,%9}, {%0,%1,%2,%3};"
                 : "+f"(c[0]), "+f"(c[1]), "+f"(c[2]), "+f"(c[3])
                 : "r"(a[0]), "r"(a[1]), "r"(a[2]), "r"(a[3]), "r"(b[0]), "r"(b[1]));
}

// ---------------- small kernels ----------------
__global__ void init_kernel() {
    int i = blockIdx.x * blockDim.x + threadIdx.x;
    if (i < ROWS_MAX) g_tok[i] = -1;
    if (i < NEXP) { g_cnt[i] = 0; g_loadf[i] = 0.0f; }
}

__global__ void gate_kernel(const float* __restrict__ x,
                            const float* __restrict__ gw,
                            const float* __restrict__ gb) {
    int gtid = blockIdx.x * blockDim.x + threadIdx.x;
    int t = gtid >> 5, lane = gtid & 31;
    if (t >= T_TOK) return;
    const float* xr = x + (size_t)t * DIM;
    float acc[NEXP];
#pragma unroll
    for (int e = 0; e < NEXP; e++) acc[e] = 0.0f;
    for (int i = lane; i < DIM; i += 32) {
        float xv = xr[i];
        const float* g = gw + (size_t)i * NEXP;
#pragma unroll
        for (int e = 0; e < NEXP; e++) acc[e] = fmaf(xv, g[e], acc[e]);
    }
#pragma unroll
    for (int e = 0; e < NEXP; e++)
#pragma unroll
        for (int o = 16; o > 0; o >>= 1)
            acc[e] += __shfl_xor_sync(0xffffffffu, acc[e], o);
    if (lane == 0) {
        float l[NEXP];
#pragma unroll
        for (int e = 0; e < NEXP; e++) l[e] = acc[e] + gb[e];
        int i0 = 0;
#pragma unroll
        for (int e = 1; e < NEXP; e++) if (l[e] > l[i0]) i0 = e;
        int i1 = -1;
#pragma unroll
        for (int e = 0; e < NEXP; e++) {
            if (e == i0) continue;
            if (i1 < 0 || l[e] > l[i1]) i1 = e;
        }
        float e1 = expf(l[i1] - l[i0]);
        float s = 1.0f + e1;
        g_topk[2 * t] = i0;  g_topk[2 * t + 1] = i1;
        g_probs[2 * t] = 1.0f / s;  g_probs[2 * t + 1] = e1 / s;
        atomicAdd(&g_cnt[i0], 1);  atomicAdd(&g_cnt[i1], 1);
        atomicAdd(&g_loadf[i0], 1.0f / s);  atomicAdd(&g_loadf[i1], e1 / s);
    }
}

__global__ void finalize_gate_kernel(float* __restrict__ out, long long out_size) {
    if (threadIdx.x == 0 && blockIdx.x == 0) {
        int off = 0;
        for (int e = 0; e < NEXP; e++) {
            g_off[e] = off;  g_cursor[e] = off;
            off += ((g_cnt[e] + BM - 1) / BM) * BM;
        }
        g_off[NEXP] = off;
        if (out_size >= (long long)T_TOK * DIM + 1 + NEXP) {
            float* tail = out + (size_t)T_TOK * DIM;
            float loss = 0.0f;
            for (int e = 0; e < NEXP; e++) {
                float le = g_loadf[e] / (float)T_TOK;
                tail[1 + e] = le;
                float d = le - 1.0f / (float)NEXP;
                loss += d * d;
            }
            tail[0] = 0.01f * loss;
        }
    }
}

__global__ void scatter_kernel() {
    int i = blockIdx.x * blockDim.x + threadIdx.x;
    if (i >= T_TOK * TOPK) return;
    int e = g_topk[i];
    int r = atomicAdd(&g_cursor[e], 1);
    g_tok[r] = i >> 1;
    g_row_of[i] = r;
}

// ONE launch: x -> g_xh, w1 -> g_w1h, w2 -> g_w2h (fp16 round)
#define X4  ((size_t)T_TOK * DIM / 4)
#define W4  ((size_t)NEXP * DIM * HID / 4)
__global__ void split_all_kernel(const float* __restrict__ x,
                                 const float* __restrict__ w1,
                                 const float* __restrict__ w2) {
    size_t i = (size_t)blockIdx.x * blockDim.x + threadIdx.x;
    if (i >= X4 + 2 * W4) return;
    const float* src;
    __half* dst;
    size_t k;
    if (i < X4)            { src = x;  dst = g_xh;  k = i; }
    else if (i < X4 + W4)  { src = w1; dst = g_w1h; k = i - X4; }
    else                   { src = w2; dst = g_w2h; k = i - X4 - W4; }
    float4 v = ((const float4*)src)[k];
    uint2 ph;
    ph.x = ((uint32_t)__half_as_ushort(__float2half_rn(v.y)) << 16) | __half_as_ushort(__float2half_rn(v.x));
    ph.y = ((uint32_t)__half_as_ushort(__float2half_rn(v.w)) << 16) | __half_as_ushort(__float2half_rn(v.z));
    ((uint2*)dst)[k] = ph;
}

// ---------------- HMMA grouped GEMM (fp16 single-pass, BK=64, 3-stage, 2 CTA/SM) ----
__global__ void __launch_bounds__(256, 2)
moe_gemm_kernel(const float* __restrict__ bias, int K, int Ntot, int mode) {
    extern __shared__ __align__(1024) char smem[];
    int row0 = blockIdx.y * BM;
    if (row0 >= g_off[NEXP]) return;
    int col0 = blockIdx.x * BN;

    int tid = threadIdx.x;
    int wid = tid >> 5, lane = tid & 31;
    int wm = wid & 3, wn = wid >> 2;

    uint32_t sdata = smem_u32(smem) + SM_HDR;
    int* s_tok = (int*)smem;

    int e = 0;
#pragma unroll
    for (int i = 0; i < NEXP; i++) if (row0 >= g_off[i + 1]) e++;

    if (mode == 1 && tid < BM) s_tok[tid] = g_tok[row0 + tid];
    __syncthreads();

    const __half* Wh = ((mode == 1) ? g_w1h : g_w2h) + (size_t)e * K * Ntot;

    const int NC = K / BK;

    auto issue = [&](int c) {
        if (c < NC) {
            uint32_t sb = sdata + (c % STAGES) * SSTRIDE;
            int k0 = c * BK;
            // A: 128 rows x 64 fp16 = 1024 chunks of 16B
#pragma unroll
            for (int i = 0; i < 4; i++) {
                int j = i * 256 + tid;
                int ar = j >> 3, ac = (j & 7) * 8;
                uint32_t dA = sb + OFF_A + (uint32_t)(ar * AP + ac) * 2;
                if (mode == 1) {
                    int tk = s_tok[ar];
                    int sz = (tk >= 0) ? 16 : 0;
                    size_t so = (size_t)(tk >= 0 ? tk : 0) * DIM + k0 + ac;
                    cp16z(dA, g_xh + so, sz);
                } else {
                    cp16(dA, g_hh + (size_t)(row0 + ar) * HID + k0 + ac);
                }
            }
            // B: 64 rows x 128 fp16 = 1024 chunks
#pragma unroll
            for (int i = 0; i < 4; i++) {
                int j = i * 256 + tid;
                int br = j >> 4, bc = (j & 15) * 8;
                uint32_t dB = sb + OFF_B + (uint32_t)(br * BP + bc) * 2;
                cp16(dB, Wh + (size_t)(k0 + br) * Ntot + col0 + bc);
            }
        }
        CP_COMMIT();
    };

    float acc[2][8][4];
#pragma unroll
    for (int mf = 0; mf < 2; mf++)
#pragma unroll
        for (int nf = 0; nf < 8; nf++)
#pragma unroll
            for (int q = 0; q < 4; q++) acc[mf][nf][q] = 0.0f;

    issue(0);
    issue(1);

    for (int c = 0; c < NC; c++) {
        CP_WAIT1();
        __syncthreads();
        uint32_t sb = sdata + (c % STAGES) * SSTRIDE;

#pragma unroll
        for (int ks = 0; ks < 4; ks++) {
            uint32_t ah[2][4];
#pragma unroll
            for (int mf = 0; mf < 2; mf++) {
                uint32_t off = (uint32_t)((wm * 32 + mf * 16 + (lane & 15)) * AP
                                          + ks * 16 + (lane >> 4) * 8) * 2;
                ldm_x4(ah[mf], sb + OFF_A + off);
            }
            uint32_t bh[8][2];
#pragma unroll
            for (int ng = 0; ng < 4; ng++) {
                uint32_t off = (uint32_t)((ks * 16 + (lane & 15)) * BP
                                          + wn * 64 + ng * 16 + (lane >> 4) * 8) * 2;
                uint32_t r[4];
                ldm_x4_t(r, sb + OFF_B + off);
                bh[2 * ng][0] = r[0]; bh[2 * ng][1] = r[1];
                bh[2 * ng + 1][0] = r[2]; bh[2 * ng + 1][1] = r[3];
            }
#pragma unroll
            for (int mf = 0; mf < 2; mf++)
#pragma unroll
                for (int nf = 0; nf < 8; nf++)
                    mma_f16(acc[mf][nf], ah[mf], bh[nf]);
        }
        issue(c + 2);
    }

    // ---- epilogue ----
    int grow = lane >> 2;
    int gcol = (lane & 3) * 2;
    if (mode == 1) {
#pragma unroll
        for (int nf = 0; nf < 8; nf++) {
            int col = col0 + wn * 64 + nf * 8 + gcol;
            float b0 = bias[(size_t)e * Ntot + col];
            float b1 = bias[(size_t)e * Ntot + col + 1];
#pragma unroll
            for (int mf = 0; mf < 2; mf++) {
                int rb = row0 + wm * 32 + mf * 16 + grow;
#pragma unroll
                for (int h = 0; h < 2; h++) {
                    int r = rb + h * 8;
                    float v0 = acc[mf][nf][2 * h]     + b0;
                    float v1 = acc[mf][nf][2 * h + 1] + b1;
                    v0 = 0.5f * v0 * (1.0f + erff(v0 * 0.70710678118654752f));
                    v1 = 0.5f * v1 * (1.0f + erff(v1 * 0.70710678118654752f));
                    uint32_t ph = ((uint32_t)__half_as_ushort(__float2half_rn(v1)) << 16)
                                  | __half_as_ushort(__float2half_rn(v0));
                    *(uint32_t*)(g_hh + (size_t)r * HID + col) = ph;
                }
            }
        }
    } else {
#pragma unroll
        for (int nf = 0; nf < 8; nf++) {
            int col = col0 + wn * 64 + nf * 8 + gcol;
#pragma unroll
            for (int mf = 0; mf < 2; mf++) {
                int rb = row0 + wm * 32 + mf * 16 + grow;
#pragma unroll
                for (int h = 0; h < 2; h++) {
                    int r = rb + h * 8;
                    float2 v = make_float2(acc[mf][nf][2 * h], acc[mf][nf][2 * h + 1]);
                    *(float2*)(g_o2 + (size_t)r * DIM + col) = v;
                }
            }
        }
    }
}

// ---------------- combine ----------------
__global__ void combine_kernel(const float* __restrict__ b2,
                               float* __restrict__ out) {
    int i4 = blockIdx.x * blockDim.x + threadIdx.x;
    const int D4 = DIM / 4;
    if (i4 >= T_TOK * D4) return;
    int t = i4 / D4;
    int d = (i4 - t * D4) * 4;
    int r0 = g_row_of[2 * t], r1 = g_row_of[2 * t + 1];
    int e0 = g_topk[2 * t],  e1 = g_topk[2 * t + 1];
    float p0 = g_probs[2 * t], p1 = g_probs[2 * t + 1];
    float4 a0 = *(const float4*)(g_o2 + (size_t)r0 * DIM + d);
    float4 a1 = *(const float4*)(g_o2 + (size_t)r1 * DIM + d);
    float4 c0 = *(const float4*)(b2 + (size_t)e0 * DIM + d);
    float4 c1 = *(const float4*)(b2 + (size_t)e1 * DIM + d);
    float4 o;
    o.x = p0 * (a0.x + c0.x) + p1 * (a1.x + c1.x);
    o.y = p0 * (a0.y + c0.y) + p1 * (a1.y + c1.y);
    o.z = p0 * (a0.z + c0.z) + p1 * (a1.z + c1.z);
    o.w = p0 * (a0.w + c0.w) + p1 * (a1.w + c1.w);
    *(float4*)(out + (size_t)t * DIM + d) = o;
}

// ---------------- launch ----------------
extern "C" void kernel_launch(void* const* d_in, const int* in_sizes, int n_in,
                              void* d_out, int out_size) {
    const float* x      = (const float*)d_in[0];
    const float* gate_w = (const float*)d_in[1];
    const float* gate_b = (const float*)d_in[2];
    const float* w1     = (const float*)d_in[3];
    const float* b1     = (const float*)d_in[4];
    const float* w2     = (const float*)d_in[5];
    const float* b2     = (const float*)d_in[6];
    float* out = (float*)d_out;

    cudaFuncSetAttribute(moe_gemm_kernel,
                         cudaFuncAttributeMaxDynamicSharedMemorySize, SMEM_TOTAL);

    init_kernel<<<(ROWS_MAX + 255) / 256, 256>>>();
    gate_kernel<<<(T_TOK * 32) / 256, 256>>>(x, gate_w, gate_b);
    finalize_gate_kernel<<<1, 32>>>(out, (long long)out_size);
    scatter_kernel<<<(T_TOK * TOPK + 255) / 256, 256>>>();
    {
        size_t total = X4 + 2 * W4;
        split_all_kernel<<<(unsigned)((total + 255) / 256), 256>>>(x, w1, w2);
    }
    {
        dim3 grid(HID / BN, ROWS_MAX / BM);
        moe_gemm_kernel<<<grid, 256, SMEM_TOTAL>>>(b1, DIM, HID, 1);
    }
    {
        dim3 grid(DIM / BN, ROWS_MAX / BM);
        moe_gemm_kernel<<<grid, 256, SMEM_TOTAL>>>(b2, HID, DIM, 2);
    }
    combine_kernel<<<(T_TOK * (DIM / 4) + 255) / 256, 256>>>(b2, out);
}